// round 1
// baseline (speedup 1.0000x reference)
#include <cuda_runtime.h>
#include <cuda_bf16.h>
#include <math.h>

// Problem constants (match reference)
#define NN 100000      // nodes
#define FF 128         // node features
#define HH 128         // hidden
#define EE 1600000     // edges
#define BB 65536       // queries
#define TD 64          // H/2
#define PIN 448        // 2H + H + TD

// ---------------- scratch (static device memory; no allocation) --------------
__device__ float g_dinv[NN];                 // deg -> rsqrt(deg), in place
__device__ float g_hw  [(size_t)NN * HH];    // h @ W
__device__ float g_agg [(size_t)NN * HH];    // aggregated messages
__device__ float g_h   [(size_t)NN * HH];    // activations
__device__ float g_tin [(size_t)BB * HH];    // [day||time] embedding input
__device__ float g_temp[(size_t)BB * HH];    // temporal = relu(tin@Wf+bf)
__device__ float g_comb[(size_t)BB * PIN];   // [route||temporal||mode]
__device__ float g_z1  [(size_t)BB * 256];
__device__ float g_z2  [(size_t)BB * 128];
__device__ float g_z3  [(size_t)BB * 64];

// ---------------- degree / normalization ------------------------------------
__global__ void deg_init_kernel(float* deg) {
    int i = blockIdx.x * blockDim.x + threadIdx.x;
    if (i < NN) deg[i] = 1.0f;   // self-loop
}
__global__ void deg_count_kernel(const int* __restrict__ dst, float* deg) {
    int e = blockIdx.x * blockDim.x + threadIdx.x;
    if (e < EE) atomicAdd(&deg[dst[e]], 1.0f);
}
__global__ void deg_finalize_kernel(float* dinv) {
    int i = blockIdx.x * blockDim.x + threadIdx.x;
    if (i < NN) dinv[i] = rsqrtf(dinv[i]);
}

// ---------------- generic fp32 GEMM  C = A[M,K] @ W[K,N] (+bias)(+act) -------
// act: 0 = none, 1 = relu
__global__ void sgemm_kernel(const float* __restrict__ A,
                             const float* __restrict__ W,
                             const float* __restrict__ bias,
                             float* __restrict__ C,
                             int M, int N, int K, int act) {
    __shared__ float As[8][128];
    __shared__ float Bs[8][132];

    int tid = threadIdx.x;          // 256 threads
    int tx = tid & 15;              // 16 col-threads
    int ty = tid >> 4;              // 16 row-threads
    int rowBase = blockIdx.y * 128;
    int colBase = blockIdx.x * 128;
    int row0 = rowBase + ty * 8;
    int col0 = colBase + tx * 8;

    float acc[8][8];
    #pragma unroll
    for (int i = 0; i < 8; i++)
        #pragma unroll
        for (int j = 0; j < 8; j++) acc[i][j] = 0.0f;

    for (int k0 = 0; k0 < K; k0 += 8) {
        // A tile: 128 rows x 8 k (transposed into As[k][row])
        #pragma unroll 4
        for (int i = tid; i < 128 * 8; i += 256) {
            int r = i >> 3, kk = i & 7;
            int gr = rowBase + r;
            As[kk][r] = (gr < M) ? A[(size_t)gr * K + k0 + kk] : 0.0f;
        }
        // B tile: 8 k x 128 cols
        #pragma unroll 4
        for (int i = tid; i < 8 * 128; i += 256) {
            int kk = i >> 7, c = i & 127;
            int gc = colBase + c;
            Bs[kk][c] = (gc < N) ? W[(size_t)(k0 + kk) * N + gc] : 0.0f;
        }
        __syncthreads();
        #pragma unroll
        for (int kk = 0; kk < 8; kk++) {
            float a[8], b[8];
            #pragma unroll
            for (int i = 0; i < 8; i++) a[i] = As[kk][ty * 8 + i];
            #pragma unroll
            for (int j = 0; j < 8; j++) b[j] = Bs[kk][tx * 8 + j];
            #pragma unroll
            for (int i = 0; i < 8; i++)
                #pragma unroll
                for (int j = 0; j < 8; j++)
                    acc[i][j] = fmaf(a[i], b[j], acc[i][j]);
        }
        __syncthreads();
    }

    #pragma unroll
    for (int i = 0; i < 8; i++) {
        int r = row0 + i;
        if (r >= M) break;
        #pragma unroll
        for (int j = 0; j < 8; j++) {
            int c = col0 + j;
            if (c >= N) continue;
            float v = acc[i][j];
            if (bias) v += bias[c];
            if (act == 1) v = fmaxf(v, 0.0f);
            C[(size_t)r * N + c] = v;
        }
    }
}

// ---------------- GCN edge aggregation ---------------------------------------
// agg init with self-loop term: agg = hw * dinv^2
__global__ void selfloop_init_kernel(const float* __restrict__ hw,
                                     const float* __restrict__ dinv,
                                     float* __restrict__ agg) {
    size_t idx = (size_t)blockIdx.x * blockDim.x + threadIdx.x;
    if (idx < (size_t)NN * HH) {
        int n = (int)(idx >> 7);
        float di = dinv[n];
        agg[idx] = hw[idx] * di * di;
    }
}

// one warp per edge, 4 floats per lane (float4 gather + 4 scalar atomics)
__global__ void edge_agg_kernel(const int* __restrict__ src,
                                const int* __restrict__ dst,
                                const float* __restrict__ dinv,
                                const float* __restrict__ hw,
                                float* __restrict__ agg) {
    int gtid = blockIdx.x * blockDim.x + threadIdx.x;
    int e = gtid >> 5;
    if (e >= EE) return;
    int lane = gtid & 31;
    int s = src[e];
    int d = dst[e];
    float c = dinv[s] * dinv[d];
    const float4* h4 = (const float4*)(hw + (size_t)s * HH);
    float4 v = h4[lane];
    float* a = agg + (size_t)d * HH + lane * 4;
    atomicAdd(a + 0, v.x * c);
    atomicAdd(a + 1, v.y * c);
    atomicAdd(a + 2, v.z * c);
    atomicAdd(a + 3, v.w * c);
}

// h = relu(agg + b)
__global__ void bias_relu_kernel(const float* __restrict__ agg,
                                 const float* __restrict__ b,
                                 float* __restrict__ h) {
    size_t idx = (size_t)blockIdx.x * blockDim.x + threadIdx.x;
    if (idx < (size_t)NN * HH)
        h[idx] = fmaxf(agg[idx] + b[idx & 127], 0.0f);
}

// ---------------- head: gathers ----------------------------------------------
__global__ void build_tin_kernel(const int* __restrict__ day_ids,
                                 const int* __restrict__ time_ids,
                                 const float* __restrict__ day_table,
                                 const float* __restrict__ time_table,
                                 float* __restrict__ tin) {
    size_t idx = (size_t)blockIdx.x * blockDim.x + threadIdx.x;
    if (idx >= (size_t)BB * HH) return;
    int r = (int)(idx >> 7);
    int c = (int)(idx & 127);
    float v;
    if (c < TD) v = day_table[day_ids[r] * TD + c];
    else        v = time_table[time_ids[r] * TD + (c - TD)];
    tin[idx] = v;
}

__global__ void build_comb_kernel(const int* __restrict__ orig,
                                  const int* __restrict__ dest,
                                  const int* __restrict__ mode_ids,
                                  const float* __restrict__ h,
                                  const float* __restrict__ temporal,
                                  const float* __restrict__ mode_table,
                                  float* __restrict__ comb) {
    size_t idx = (size_t)blockIdx.x * blockDim.x + threadIdx.x;
    if (idx >= (size_t)BB * PIN) return;
    int r = (int)(idx / PIN);
    int c = (int)(idx % PIN);
    float v;
    if (c < 128)       v = h[(size_t)orig[r] * HH + c];
    else if (c < 256)  v = h[(size_t)dest[r] * HH + (c - 128)];
    else if (c < 384)  v = temporal[(size_t)r * HH + (c - 256)];
    else               v = mode_table[mode_ids[r] * TD + (c - 384)];
    comb[idx] = v;
}

// ---------------- final: out = sigmoid(z3 @ Wh4 + bh4), one warp per row -----
__global__ void head_final_kernel(const float* __restrict__ z3,
                                  const float* __restrict__ Wh4,
                                  const float* __restrict__ bh4,
                                  float* __restrict__ out) {
    int gtid = blockIdx.x * blockDim.x + threadIdx.x;
    int r = gtid >> 5;
    if (r >= BB) return;
    int lane = gtid & 31;
    const float* zr = z3 + (size_t)r * 64;
    float s = zr[lane] * Wh4[lane] + zr[32 + lane] * Wh4[32 + lane];
    #pragma unroll
    for (int o = 16; o; o >>= 1) s += __shfl_xor_sync(0xFFFFFFFFu, s, o);
    if (lane == 0) {
        float v = s + bh4[0];
        out[r] = 1.0f / (1.0f + expf(-v));
    }
}

// =============================================================================
extern "C" void kernel_launch(void* const* d_in, const int* in_sizes, int n_in,
                              void* d_out, int out_size) {
    // inputs in metadata order
    const float* x          = (const float*)d_in[0];
    const int*   edge_index = (const int*)  d_in[1];   // [2,E]: row0=src, row1=dst
    const int*   origin_ids = (const int*)  d_in[2];
    const int*   dest_ids   = (const int*)  d_in[3];
    const int*   day_ids    = (const int*)  d_in[4];
    const int*   time_ids   = (const int*)  d_in[5];
    const int*   mode_ids   = (const int*)  d_in[6];
    const float* W1 = (const float*)d_in[7];
    const float* b1 = (const float*)d_in[8];
    const float* W2 = (const float*)d_in[9];
    const float* b2 = (const float*)d_in[10];
    const float* W3 = (const float*)d_in[11];
    const float* b3 = (const float*)d_in[12];
    const float* day_table  = (const float*)d_in[13];
    const float* time_table = (const float*)d_in[14];
    const float* mode_table = (const float*)d_in[15];
    const float* Wf  = (const float*)d_in[16];
    const float* bf  = (const float*)d_in[17];
    const float* Wh1 = (const float*)d_in[18];
    const float* bh1 = (const float*)d_in[19];
    const float* Wh2 = (const float*)d_in[20];
    const float* bh2 = (const float*)d_in[21];
    const float* Wh3 = (const float*)d_in[22];
    const float* bh3 = (const float*)d_in[23];
    const float* Wh4 = (const float*)d_in[24];
    const float* bh4 = (const float*)d_in[25];
    float* out = (float*)d_out;

    const int* src = edge_index;
    const int* dst = edge_index + EE;

    // scratch pointers (symbol address lookup is host-side, capture-safe)
    float *dinv, *hw, *agg, *h, *tin, *temp, *comb, *z1, *z2, *z3;
    cudaGetSymbolAddress((void**)&dinv, g_dinv);
    cudaGetSymbolAddress((void**)&hw,   g_hw);
    cudaGetSymbolAddress((void**)&agg,  g_agg);
    cudaGetSymbolAddress((void**)&h,    g_h);
    cudaGetSymbolAddress((void**)&tin,  g_tin);
    cudaGetSymbolAddress((void**)&temp, g_temp);
    cudaGetSymbolAddress((void**)&comb, g_comb);
    cudaGetSymbolAddress((void**)&z1,   g_z1);
    cudaGetSymbolAddress((void**)&z2,   g_z2);
    cudaGetSymbolAddress((void**)&z3,   g_z3);

    const int T = 256;
    const size_t NH = (size_t)NN * HH;

    // --- degree normalization ---
    deg_init_kernel<<<(NN + T - 1) / T, T>>>(dinv);
    deg_count_kernel<<<(EE + T - 1) / T, T>>>(dst, dinv);
    deg_finalize_kernel<<<(NN + T - 1) / T, T>>>(dinv);

    dim3 gemmBlk(256);
    dim3 gNode((HH + 127) / 128, (NN + 127) / 128);
    int  edgeBlocks = (int)(((size_t)EE * 32 + T - 1) / T);
    int  nhBlocks   = (int)((NH + T - 1) / T);

    // --- GCN layer 1 (input x) ---
    sgemm_kernel<<<gNode, gemmBlk>>>(x, W1, nullptr, hw, NN, HH, FF, 0);
    selfloop_init_kernel<<<nhBlocks, T>>>(hw, dinv, agg);
    edge_agg_kernel<<<edgeBlocks, T>>>(src, dst, dinv, hw, agg);
    bias_relu_kernel<<<nhBlocks, T>>>(agg, b1, h);

    // --- GCN layer 2 ---
    sgemm_kernel<<<gNode, gemmBlk>>>(h, W2, nullptr, hw, NN, HH, HH, 0);
    selfloop_init_kernel<<<nhBlocks, T>>>(hw, dinv, agg);
    edge_agg_kernel<<<edgeBlocks, T>>>(src, dst, dinv, hw, agg);
    bias_relu_kernel<<<nhBlocks, T>>>(agg, b2, h);

    // --- GCN layer 3 ---
    sgemm_kernel<<<gNode, gemmBlk>>>(h, W3, nullptr, hw, NN, HH, HH, 0);
    selfloop_init_kernel<<<nhBlocks, T>>>(hw, dinv, agg);
    edge_agg_kernel<<<edgeBlocks, T>>>(src, dst, dinv, hw, agg);
    bias_relu_kernel<<<nhBlocks, T>>>(agg, b3, h);

    // --- temporal fusion ---
    int bhBlocks = (int)(((size_t)BB * HH + T - 1) / T);
    build_tin_kernel<<<bhBlocks, T>>>(day_ids, time_ids, day_table, time_table, tin);
    dim3 gTemp((HH + 127) / 128, (BB + 127) / 128);
    sgemm_kernel<<<gTemp, gemmBlk>>>(tin, Wf, bf, temp, BB, HH, HH, 1);

    // --- combined features ---
    int combBlocks = (int)(((size_t)BB * PIN + T - 1) / T);
    build_comb_kernel<<<combBlocks, T>>>(origin_ids, dest_ids, mode_ids,
                                         h, temp, mode_table, comb);

    // --- prediction head ---
    dim3 gZ1((256 + 127) / 128, (BB + 127) / 128);
    sgemm_kernel<<<gZ1, gemmBlk>>>(comb, Wh1, bh1, z1, BB, 256, PIN, 1);
    dim3 gZ2((128 + 127) / 128, (BB + 127) / 128);
    sgemm_kernel<<<gZ2, gemmBlk>>>(z1, Wh2, bh2, z2, BB, 128, 256, 1);
    dim3 gZ3((64 + 127) / 128, (BB + 127) / 128);
    sgemm_kernel<<<gZ3, gemmBlk>>>(z2, Wh3, bh3, z3, BB, 64, 128, 1);

    head_final_kernel<<<(int)(((size_t)BB * 32 + T - 1) / T), T>>>(z3, Wh4, bh4, out);
}

// round 3
// speedup vs baseline: 1.6676x; 1.6676x over previous
#include <cuda_runtime.h>
#include <cuda_bf16.h>
#include <math.h>
#include <cstdint>

// Problem constants
#define NN 100000      // nodes
#define FF 128         // node features
#define HH 128         // hidden
#define EE 1600000     // edges
#define BB 65536       // queries
#define TD 64          // H/2
#define PIN 448        // 2H + H + TD

// ---------------- scratch (static device memory; no allocation) --------------
__device__ float g_dinv[NN];
__device__ float g_hw  [(size_t)NN * HH];
__device__ float g_agg [(size_t)NN * HH];
__device__ float g_h   [(size_t)NN * HH];
__device__ float g_tin [(size_t)BB * HH];
__device__ float g_temp[(size_t)BB * HH];
__device__ float g_comb[(size_t)BB * PIN];
__device__ float g_z1  [(size_t)BB * 256];
__device__ float g_z2  [(size_t)BB * 128];
__device__ float g_z3  [(size_t)BB * 64];

// ======================= HMMA helpers ========================================
__device__ __forceinline__ uint32_t smem_to_u32(const void* p) {
    uint32_t a;
    asm("{ .reg .u64 t; cvta.to.shared.u64 t, %1; cvt.u32.u64 %0, t; }"
        : "=r"(a) : "l"(p));
    return a;
}

__device__ __forceinline__ void ldm_x4(uint32_t& r0, uint32_t& r1,
                                       uint32_t& r2, uint32_t& r3, uint32_t addr) {
    asm volatile("ldmatrix.sync.aligned.m8n8.x4.shared.b16 {%0,%1,%2,%3}, [%4];"
        : "=r"(r0), "=r"(r1), "=r"(r2), "=r"(r3) : "r"(addr));
}

__device__ __forceinline__ void mma_bf16(float* c, const uint32_t* a,
                                         uint32_t b0, uint32_t b1) {
    asm volatile(
        "mma.sync.aligned.m16n8k16.row.col.f32.bf16.bf16.f32 "
        "{%0,%1,%2,%3}, {%4,%5,%6,%7}, {%8,%9}, {%0,%1,%2,%3};"
        : "+f"(c[0]), "+f"(c[1]), "+f"(c[2]), "+f"(c[3])
        : "r"(a[0]), "r"(a[1]), "r"(a[2]), "r"(a[3]), "r"(b0), "r"(b1));
}

// ======================= tensor-core GEMM ====================================
// C[M, Ntot] = A[M, K] @ W[K, Ntot]   (fp32 in, bf16 mma, fp32 accumulate)
// grid = (ceil(Ntot/128), ceil(M/128)); block = 256 threads (8 warps: 4m x 2n)
// mode 0: C = v
// mode 1: C = relu(v + bias)
// mode 2: C(hw) = v ; C2(agg) = v * dinv[row]^2   (Ntot == 128)
// K must be a multiple of 64.
#define LDBYTES 144   // 72 bf16 per smem row: 64 data + 8 pad (conflict-free ldmatrix)

__global__ void __launch_bounds__(256, 2)
tc_gemm_kernel(const float* __restrict__ A, const float* __restrict__ W,
               const float* __restrict__ bias, float* __restrict__ C,
               float* __restrict__ C2, const float* __restrict__ dinv,
               int M, int K, int Ntot, int mode) {
    __shared__ __align__(16) char smem[2 * 128 * LDBYTES];  // 36864 B
    char* sA = smem;
    char* sB = smem + 128 * LDBYTES;
    uint32_t sAu = smem_to_u32(sA);
    uint32_t sBu = smem_to_u32(sB);

    int tid = threadIdx.x;
    int wid = tid >> 5;
    int lane = tid & 31;
    int wm = wid >> 1;           // 0..3  (32 rows each)
    int wn = wid & 1;            // 0..1  (64 cols each)

    int rowBase = blockIdx.y * 128;
    int colBase = blockIdx.x * 128;

    float acc[2][8][4];
    #pragma unroll
    for (int mt = 0; mt < 2; mt++)
        #pragma unroll
        for (int nf = 0; nf < 8; nf++)
            #pragma unroll
            for (int j = 0; j < 4; j++) acc[mt][nf][j] = 0.0f;

    int lq = lane & 15;          // ldmatrix row selector
    int lh = lane >> 4;          // 0/1: k-half selector

    for (int k0 = 0; k0 < K; k0 += 64) {
        __syncthreads();
        // ---- A tile: 128 rows x 64 bf16 (K-major) ----
        #pragma unroll 4
        for (int i = tid; i < 128 * 32; i += 256) {
            int r = i >> 5, kp = i & 31;
            int gr = rowBase + r;
            float2 v = make_float2(0.f, 0.f);
            if (gr < M) v = *(const float2*)(A + (size_t)gr * K + k0 + 2 * kp);
            *(__nv_bfloat162*)(sA + r * LDBYTES + kp * 4) = __float22bfloat162_rn(v);
        }
        // ---- B tile: Bs[n][k] = W[k0+k][colBase+n], 128 n x 64 k ----
        #pragma unroll 4
        for (int i = tid; i < 64 * 128; i += 256) {
            int n = i & 127, kk = i >> 7;
            int gc = colBase + n;
            float v = (gc < Ntot) ? W[(size_t)(k0 + kk) * Ntot + gc] : 0.0f;
            *(__nv_bfloat16*)(sB + n * LDBYTES + kk * 2) = __float2bfloat16(v);
        }
        __syncthreads();

        #pragma unroll
        for (int ks = 0; ks < 4; ks++) {
            uint32_t af[2][4];
            #pragma unroll
            for (int mt = 0; mt < 2; mt++) {
                uint32_t addr = sAu + (uint32_t)(wm * 32 + mt * 16 + lq) * LDBYTES
                              + ks * 32 + lh * 16;
                ldm_x4(af[mt][0], af[mt][1], af[mt][2], af[mt][3], addr);
            }
            uint32_t bfr[8][2];
            #pragma unroll
            for (int g = 0; g < 4; g++) {
                uint32_t r0, r1, r2, r3;
                uint32_t addr = sBu + (uint32_t)(wn * 64 + g * 16 + lq) * LDBYTES
                              + ks * 32 + lh * 16;
                ldm_x4(r0, r1, r2, r3, addr);
                bfr[2 * g][0] = r0;     bfr[2 * g][1] = r2;
                bfr[2 * g + 1][0] = r1; bfr[2 * g + 1][1] = r3;
            }
            #pragma unroll
            for (int mt = 0; mt < 2; mt++)
                #pragma unroll
                for (int nf = 0; nf < 8; nf++)
                    mma_bf16(acc[mt][nf], af[mt], bfr[nf][0], bfr[nf][1]);
        }
    }

    // ---- epilogue ----
    int rowOff = lane >> 2;          // 0..7
    int colOff = (lane & 3) * 2;     // 0,2,4,6
    #pragma unroll
    for (int mt = 0; mt < 2; mt++) {
        #pragma unroll
        for (int half = 0; half < 2; half++) {   // c0/c1 vs c2/c3 (row+8)
            int r = rowBase + wm * 32 + mt * 16 + rowOff + half * 8;
            if (r >= M) continue;
            float di2 = 0.f;
            if (mode == 2) { float d = dinv[r]; di2 = d * d; }
            #pragma unroll
            for (int nf = 0; nf < 8; nf++) {
                int c = colBase + wn * 64 + nf * 8 + colOff;
                if (c >= Ntot) continue;
                float v0 = acc[mt][nf][half * 2 + 0];
                float v1 = acc[mt][nf][half * 2 + 1];
                if (mode == 1) {
                    v0 = fmaxf(v0 + bias[c], 0.f);
                    v1 = fmaxf(v1 + bias[c + 1], 0.f);
                }
                if (mode == 2) {
                    *(float2*)(C  + (size_t)r * 128 + c) = make_float2(v0, v1);
                    *(float2*)(C2 + (size_t)r * 128 + c) = make_float2(v0 * di2, v1 * di2);
                } else {
                    *(float2*)(C + (size_t)r * Ntot + c) = make_float2(v0, v1);
                }
            }
        }
    }
}

// ---------------- degree / normalization ------------------------------------
__global__ void deg_init_kernel(float* deg) {
    int i = blockIdx.x * blockDim.x + threadIdx.x;
    if (i < NN) deg[i] = 1.0f;
}
__global__ void deg_count_kernel(const int* __restrict__ dst, float* deg) {
    int e = blockIdx.x * blockDim.x + threadIdx.x;
    if (e < EE) atomicAdd(&deg[dst[e]], 1.0f);
}
__global__ void deg_finalize_kernel(float* dinv) {
    int i = blockIdx.x * blockDim.x + threadIdx.x;
    if (i < NN) dinv[i] = rsqrtf(dinv[i]);
}

// ---------------- GCN edge aggregation ---------------------------------------
__global__ void edge_agg_kernel(const int* __restrict__ src,
                                const int* __restrict__ dst,
                                const float* __restrict__ dinv,
                                const float* __restrict__ hw,
                                float* __restrict__ agg) {
    int gtid = blockIdx.x * blockDim.x + threadIdx.x;
    int e = gtid >> 5;
    if (e >= EE) return;
    int lane = gtid & 31;
    int s = src[e];
    int d = dst[e];
    float c = dinv[s] * dinv[d];
    const float4* h4 = (const float4*)(hw + (size_t)s * HH);
    float4 v = h4[lane];
    float* a = agg + (size_t)d * HH + lane * 4;
    atomicAdd(a + 0, v.x * c);
    atomicAdd(a + 1, v.y * c);
    atomicAdd(a + 2, v.z * c);
    atomicAdd(a + 3, v.w * c);
}

__global__ void bias_relu_kernel(const float* __restrict__ agg,
                                 const float* __restrict__ b,
                                 float* __restrict__ h) {
    size_t idx = (size_t)blockIdx.x * blockDim.x + threadIdx.x;
    if (idx < (size_t)NN * HH)
        h[idx] = fmaxf(agg[idx] + b[idx & 127], 0.0f);
}

// ---------------- head: gathers ----------------------------------------------
__global__ void build_tin_kernel(const int* __restrict__ day_ids,
                                 const int* __restrict__ time_ids,
                                 const float* __restrict__ day_table,
                                 const float* __restrict__ time_table,
                                 float* __restrict__ tin) {
    size_t idx = (size_t)blockIdx.x * blockDim.x + threadIdx.x;
    if (idx >= (size_t)BB * HH) return;
    int r = (int)(idx >> 7);
    int c = (int)(idx & 127);
    float v;
    if (c < TD) v = day_table[day_ids[r] * TD + c];
    else        v = time_table[time_ids[r] * TD + (c - TD)];
    tin[idx] = v;
}

__global__ void build_comb_kernel(const int* __restrict__ orig,
                                  const int* __restrict__ dest,
                                  const int* __restrict__ mode_ids,
                                  const float* __restrict__ h,
                                  const float* __restrict__ temporal,
                                  const float* __restrict__ mode_table,
                                  float* __restrict__ comb) {
    size_t idx = (size_t)blockIdx.x * blockDim.x + threadIdx.x;
    if (idx >= (size_t)BB * PIN) return;
    int r = (int)(idx / PIN);
    int c = (int)(idx % PIN);
    float v;
    if (c < 128)       v = h[(size_t)orig[r] * HH + c];
    else if (c < 256)  v = h[(size_t)dest[r] * HH + (c - 128)];
    else if (c < 384)  v = temporal[(size_t)r * HH + (c - 256)];
    else               v = mode_table[mode_ids[r] * TD + (c - 384)];
    comb[idx] = v;
}

// ---------------- final layer ------------------------------------------------
__global__ void head_final_kernel(const float* __restrict__ z3,
                                  const float* __restrict__ Wh4,
                                  const float* __restrict__ bh4,
                                  float* __restrict__ out) {
    int gtid = blockIdx.x * blockDim.x + threadIdx.x;
    int r = gtid >> 5;
    if (r >= BB) return;
    int lane = gtid & 31;
    const float* zr = z3 + (size_t)r * 64;
    float s = zr[lane] * Wh4[lane] + zr[32 + lane] * Wh4[32 + lane];
    #pragma unroll
    for (int o = 16; o; o >>= 1) s += __shfl_xor_sync(0xFFFFFFFFu, s, o);
    if (lane == 0) {
        float v = s + bh4[0];
        out[r] = 1.0f / (1.0f + expf(-v));
    }
}

// =============================================================================
extern "C" void kernel_launch(void* const* d_in, const int* in_sizes, int n_in,
                              void* d_out, int out_size) {
    const float* x          = (const float*)d_in[0];
    const int*   edge_index = (const int*)  d_in[1];
    const int*   origin_ids = (const int*)  d_in[2];
    const int*   dest_ids   = (const int*)  d_in[3];
    const int*   day_ids    = (const int*)  d_in[4];
    const int*   time_ids   = (const int*)  d_in[5];
    const int*   mode_ids   = (const int*)  d_in[6];
    const float* W1 = (const float*)d_in[7];
    const float* b1 = (const float*)d_in[8];
    const float* W2 = (const float*)d_in[9];
    const float* b2 = (const float*)d_in[10];
    const float* W3 = (const float*)d_in[11];
    const float* b3 = (const float*)d_in[12];
    const float* day_table  = (const float*)d_in[13];
    const float* time_table = (const float*)d_in[14];
    const float* mode_table = (const float*)d_in[15];
    const float* Wf  = (const float*)d_in[16];
    const float* bf  = (const float*)d_in[17];
    const float* Wh1 = (const float*)d_in[18];
    const float* bh1 = (const float*)d_in[19];
    const float* Wh2 = (const float*)d_in[20];
    const float* bh2 = (const float*)d_in[21];
    const float* Wh3 = (const float*)d_in[22];
    const float* bh3 = (const float*)d_in[23];
    const float* Wh4 = (const float*)d_in[24];
    const float* bh4 = (const float*)d_in[25];
    float* out = (float*)d_out;

    const int* src = edge_index;
    const int* dst = edge_index + EE;

    float *dinv, *hw, *agg, *h, *tin, *temp, *comb, *z1, *z2, *z3;
    cudaGetSymbolAddress((void**)&dinv, g_dinv);
    cudaGetSymbolAddress((void**)&hw,   g_hw);
    cudaGetSymbolAddress((void**)&agg,  g_agg);
    cudaGetSymbolAddress((void**)&h,    g_h);
    cudaGetSymbolAddress((void**)&tin,  g_tin);
    cudaGetSymbolAddress((void**)&temp, g_temp);
    cudaGetSymbolAddress((void**)&comb, g_comb);
    cudaGetSymbolAddress((void**)&z1,   g_z1);
    cudaGetSymbolAddress((void**)&z2,   g_z2);
    cudaGetSymbolAddress((void**)&z3,   g_z3);

    const int T = 256;
    const size_t NH = (size_t)NN * HH;
    int nhBlocks   = (int)((NH + T - 1) / T);
    int edgeBlocks = (int)(((size_t)EE * 32 + T - 1) / T);

    // --- degree normalization ---
    deg_init_kernel<<<(NN + T - 1) / T, T>>>(dinv);
    deg_count_kernel<<<(EE + T - 1) / T, T>>>(dst, dinv);
    deg_finalize_kernel<<<(NN + T - 1) / T, T>>>(dinv);

    dim3 blk(256);
    dim3 gNode(1, (NN + 127) / 128);       // 782
    dim3 gHead(1, (BB + 127) / 128);       // 512

    // --- GCN layer 1 ---
    tc_gemm_kernel<<<gNode, blk>>>(x, W1, nullptr, hw, agg, dinv, NN, FF, HH, 2);
    edge_agg_kernel<<<edgeBlocks, T>>>(src, dst, dinv, hw, agg);
    bias_relu_kernel<<<nhBlocks, T>>>(agg, b1, h);
    // --- GCN layer 2 ---
    tc_gemm_kernel<<<gNode, blk>>>(h, W2, nullptr, hw, agg, dinv, NN, HH, HH, 2);
    edge_agg_kernel<<<edgeBlocks, T>>>(src, dst, dinv, hw, agg);
    bias_relu_kernel<<<nhBlocks, T>>>(agg, b2, h);
    // --- GCN layer 3 ---
    tc_gemm_kernel<<<gNode, blk>>>(h, W3, nullptr, hw, agg, dinv, NN, HH, HH, 2);
    edge_agg_kernel<<<edgeBlocks, T>>>(src, dst, dinv, hw, agg);
    bias_relu_kernel<<<nhBlocks, T>>>(agg, b3, h);

    // --- temporal fusion ---
    int bhBlocks = (int)(((size_t)BB * HH + T - 1) / T);
    build_tin_kernel<<<bhBlocks, T>>>(day_ids, time_ids, day_table, time_table, tin);
    tc_gemm_kernel<<<gHead, blk>>>(tin, Wf, bf, temp, nullptr, nullptr, BB, HH, HH, 1);

    // --- combined features ---
    int combBlocks = (int)(((size_t)BB * PIN + T - 1) / T);
    build_comb_kernel<<<combBlocks, T>>>(origin_ids, dest_ids, mode_ids,
                                         h, temp, mode_table, comb);

    // --- prediction head ---
    dim3 gZ1(2, (BB + 127) / 128);
    tc_gemm_kernel<<<gZ1, blk>>>(comb, Wh1, bh1, z1, nullptr, nullptr, BB, PIN, 256, 1);
    tc_gemm_kernel<<<gHead, blk>>>(z1, Wh2, bh2, z2, nullptr, nullptr, BB, 256, 128, 1);
    tc_gemm_kernel<<<gHead, blk>>>(z2, Wh3, bh3, z3, nullptr, nullptr, BB, 128, 64, 1);

    head_final_kernel<<<(int)(((size_t)BB * 32 + T - 1) / T), T>>>(z3, Wh4, bh4, out);
}

// round 4
// speedup vs baseline: 3.0754x; 1.8442x over previous
#include <cuda_runtime.h>
#include <cuda_bf16.h>
#include <math.h>
#include <cstdint>

// Problem constants
#define NN 100000      // nodes
#define FF 128         // node features
#define HH 128         // hidden
#define EE 1600000     // edges
#define BB 65536       // queries
#define TD 64          // H/2
#define PIN 448        // 2H + H + TD

#define SCAN_B 1024
#define NBLK_SCAN ((NN + SCAN_B - 1) / SCAN_B)   // 98

// ---------------- scratch (static device memory; no allocation) --------------
__device__ float g_dinv[NN];
__device__ int   g_cnt  [NN];
__device__ int   g_rowp [NN + 1];
__device__ int   g_cursor[NN];
__device__ int   g_bsum [NBLK_SCAN + 1];
__device__ int   g_csr_src [EE];
__device__ float g_csr_coef[EE];
__device__ float g_hw  [(size_t)NN * HH];
__device__ float g_h   [(size_t)NN * HH];
__device__ float g_tin [(size_t)BB * HH];
__device__ float g_temp[(size_t)BB * HH];
__device__ float g_comb[(size_t)BB * PIN];
__device__ float g_z1  [(size_t)BB * 256];
__device__ float g_z2  [(size_t)BB * 128];
__device__ float g_z3  [(size_t)BB * 64];

// ======================= HMMA helpers ========================================
__device__ __forceinline__ uint32_t smem_to_u32(const void* p) {
    uint32_t a;
    asm("{ .reg .u64 t; cvta.to.shared.u64 t, %1; cvt.u32.u64 %0, t; }"
        : "=r"(a) : "l"(p));
    return a;
}
__device__ __forceinline__ void ldm_x4(uint32_t& r0, uint32_t& r1,
                                       uint32_t& r2, uint32_t& r3, uint32_t addr) {
    asm volatile("ldmatrix.sync.aligned.m8n8.x4.shared.b16 {%0,%1,%2,%3}, [%4];"
        : "=r"(r0), "=r"(r1), "=r"(r2), "=r"(r3) : "r"(addr));
}
__device__ __forceinline__ void mma_bf16(float* c, const uint32_t* a,
                                         uint32_t b0, uint32_t b1) {
    asm volatile(
        "mma.sync.aligned.m16n8k16.row.col.f32.bf16.bf16.f32 "
        "{%0,%1,%2,%3}, {%4,%5,%6,%7}, {%8,%9}, {%0,%1,%2,%3};"
        : "+f"(c[0]), "+f"(c[1]), "+f"(c[2]), "+f"(c[3])
        : "r"(a[0]), "r"(a[1]), "r"(a[2]), "r"(a[3]), "r"(b0), "r"(b1));
}

// ======================= tensor-core GEMM ====================================
// C[M, Ntot] = A[M, K] @ W[K, Ntot]   (fp32 in, bf16 mma, fp32 accumulate)
// mode 0: C = v      mode 1: C = relu(v + bias)
#define LDBYTES 144

__global__ void __launch_bounds__(256, 2)
tc_gemm_kernel(const float* __restrict__ A, const float* __restrict__ W,
               const float* __restrict__ bias, float* __restrict__ C,
               int M, int K, int Ntot, int mode) {
    __shared__ __align__(16) char smem[2 * 128 * LDBYTES];
    char* sA = smem;
    char* sB = smem + 128 * LDBYTES;
    uint32_t sAu = smem_to_u32(sA);
    uint32_t sBu = smem_to_u32(sB);

    int tid = threadIdx.x;
    int wid = tid >> 5;
    int lane = tid & 31;
    int wm = wid >> 1;
    int wn = wid & 1;

    int rowBase = blockIdx.y * 128;
    int colBase = blockIdx.x * 128;

    float acc[2][8][4];
    #pragma unroll
    for (int mt = 0; mt < 2; mt++)
        #pragma unroll
        for (int nf = 0; nf < 8; nf++)
            #pragma unroll
            for (int j = 0; j < 4; j++) acc[mt][nf][j] = 0.0f;

    int lq = lane & 15;
    int lh = lane >> 4;

    for (int k0 = 0; k0 < K; k0 += 64) {
        __syncthreads();
        #pragma unroll 4
        for (int i = tid; i < 128 * 32; i += 256) {
            int r = i >> 5, kp = i & 31;
            int gr = rowBase + r;
            float2 v = make_float2(0.f, 0.f);
            if (gr < M) v = *(const float2*)(A + (size_t)gr * K + k0 + 2 * kp);
            *(__nv_bfloat162*)(sA + r * LDBYTES + kp * 4) = __float22bfloat162_rn(v);
        }
        #pragma unroll 4
        for (int i = tid; i < 64 * 128; i += 256) {
            int n = i & 127, kk = i >> 7;
            int gc = colBase + n;
            float v = (gc < Ntot) ? W[(size_t)(k0 + kk) * Ntot + gc] : 0.0f;
            *(__nv_bfloat16*)(sB + n * LDBYTES + kk * 2) = __float2bfloat16(v);
        }
        __syncthreads();

        #pragma unroll
        for (int ks = 0; ks < 4; ks++) {
            uint32_t af[2][4];
            #pragma unroll
            for (int mt = 0; mt < 2; mt++) {
                uint32_t addr = sAu + (uint32_t)(wm * 32 + mt * 16 + lq) * LDBYTES
                              + ks * 32 + lh * 16;
                ldm_x4(af[mt][0], af[mt][1], af[mt][2], af[mt][3], addr);
            }
            uint32_t bfr[8][2];
            #pragma unroll
            for (int g = 0; g < 4; g++) {
                uint32_t r0, r1, r2, r3;
                uint32_t addr = sBu + (uint32_t)(wn * 64 + g * 16 + lq) * LDBYTES
                              + ks * 32 + lh * 16;
                ldm_x4(r0, r1, r2, r3, addr);
                bfr[2 * g][0] = r0;     bfr[2 * g][1] = r2;
                bfr[2 * g + 1][0] = r1; bfr[2 * g + 1][1] = r3;
            }
            #pragma unroll
            for (int mt = 0; mt < 2; mt++)
                #pragma unroll
                for (int nf = 0; nf < 8; nf++)
                    mma_bf16(acc[mt][nf], af[mt], bfr[nf][0], bfr[nf][1]);
        }
    }

    int rowOff = lane >> 2;
    int colOff = (lane & 3) * 2;
    #pragma unroll
    for (int mt = 0; mt < 2; mt++) {
        #pragma unroll
        for (int half = 0; half < 2; half++) {
            int r = rowBase + wm * 32 + mt * 16 + rowOff + half * 8;
            if (r >= M) continue;
            #pragma unroll
            for (int nf = 0; nf < 8; nf++) {
                int c = colBase + wn * 64 + nf * 8 + colOff;
                if (c >= Ntot) continue;
                float v0 = acc[mt][nf][half * 2 + 0];
                float v1 = acc[mt][nf][half * 2 + 1];
                if (mode == 1) {
                    v0 = fmaxf(v0 + bias[c], 0.f);
                    v1 = fmaxf(v1 + bias[c + 1], 0.f);
                }
                *(float2*)(C + (size_t)r * Ntot + c) = make_float2(v0, v1);
            }
        }
    }
}

// ======================= CSR build ===========================================
__global__ void cnt_zero_kernel(int* cnt) {
    int i = blockIdx.x * blockDim.x + threadIdx.x;
    if (i < NN) cnt[i] = 0;
}
__global__ void cnt_count_kernel(const int* __restrict__ dst, int* cnt) {
    int e = blockIdx.x * blockDim.x + threadIdx.x;
    if (e < EE) atomicAdd(&cnt[dst[e]], 1);
}
__global__ void dinv_kernel(const int* __restrict__ cnt, float* dinv) {
    int i = blockIdx.x * blockDim.x + threadIdx.x;
    if (i < NN) dinv[i] = rsqrtf((float)cnt[i] + 1.0f);
}
// block-level inclusive scan -> exclusive per-element, block totals to bsum
__global__ void scan_block_kernel(const int* __restrict__ cnt, int* excl, int* bsum) {
    __shared__ int s[SCAN_B];
    int tid = threadIdx.x;
    int i = blockIdx.x * SCAN_B + tid;
    int v = (i < NN) ? cnt[i] : 0;
    s[tid] = v;
    __syncthreads();
    for (int off = 1; off < SCAN_B; off <<= 1) {
        int t = (tid >= off) ? s[tid - off] : 0;
        __syncthreads();
        s[tid] += t;
        __syncthreads();
    }
    if (i < NN) excl[i] = s[tid] - v;
    if (tid == SCAN_B - 1) bsum[blockIdx.x] = s[tid];
}
__global__ void scan_bsum_kernel(int* bsum) {   // single block, exclusive scan
    __shared__ int s[NBLK_SCAN];
    int tid = threadIdx.x;
    int v = (tid < NBLK_SCAN) ? bsum[tid] : 0;
    if (tid < NBLK_SCAN) s[tid] = v;
    __syncthreads();
    if (tid == 0) {
        int run = 0;
        for (int b = 0; b < NBLK_SCAN; b++) { int t = s[b]; s[b] = run; run += t; }
    }
    __syncthreads();
    if (tid < NBLK_SCAN) bsum[tid] = s[tid];
}
__global__ void scan_add_kernel(int* rowp, const int* __restrict__ bsum, int* cursor) {
    int i = blockIdx.x * blockDim.x + threadIdx.x;
    if (i < NN) {
        int v = rowp[i] + bsum[i / SCAN_B];
        rowp[i] = v;
        cursor[i] = v;
    }
    if (i == 0) rowp[NN] = EE;
}
__global__ void scatter_kernel(const int* __restrict__ src, const int* __restrict__ dst,
                               const float* __restrict__ dinv,
                               int* cursor, int* csr_src, float* csr_coef) {
    int e = blockIdx.x * blockDim.x + threadIdx.x;
    if (e >= EE) return;
    int s = src[e], d = dst[e];
    int p = atomicAdd(&cursor[d], 1);
    csr_src[p] = s;
    csr_coef[p] = dinv[s] * dinv[d];
}

// ============== fused aggregation: h = relu(D^-1/2 (A+I) D^-1/2 hw + b) ======
// one warp per (node, 32-col group); 4 warps/node; 256-thread blocks
__global__ void __launch_bounds__(256)
agg_fused_kernel(const int* __restrict__ rowp,
                 const int* __restrict__ csr_src,
                 const float* __restrict__ csr_coef,
                 const float* __restrict__ dinv,
                 const float* __restrict__ hw,
                 const float* __restrict__ bias,
                 float* __restrict__ h) {
    int gw = (blockIdx.x * blockDim.x + threadIdx.x) >> 5;
    int node = gw >> 2;
    if (node >= NN) return;
    int grp = gw & 3;
    int lane = threadIdx.x & 31;
    int col = grp * 32 + lane;

    int beg = rowp[node], end = rowp[node + 1];
    float sum = 0.0f;
    for (int i = beg; i < end; i += 32) {
        int n = end - i; if (n > 32) n = 32;
        int sidx = 0; float cf = 0.0f;
        if (lane < n) { sidx = csr_src[i + lane]; cf = csr_coef[i + lane]; }
        #pragma unroll 4
        for (int j = 0; j < n; j++) {
            int s   = __shfl_sync(0xFFFFFFFFu, sidx, j);
            float c = __shfl_sync(0xFFFFFFFFu, cf, j);
            sum = fmaf(hw[(size_t)s * HH + col], c, sum);
        }
    }
    float di = dinv[node];
    sum = fmaf(hw[(size_t)node * HH + col], di * di, sum);
    h[(size_t)node * HH + col] = fmaxf(sum + bias[col], 0.0f);
}

// ---------------- head: gathers ----------------------------------------------
__global__ void build_tin_kernel(const int* __restrict__ day_ids,
                                 const int* __restrict__ time_ids,
                                 const float* __restrict__ day_table,
                                 const float* __restrict__ time_table,
                                 float* __restrict__ tin) {
    size_t idx = (size_t)blockIdx.x * blockDim.x + threadIdx.x;
    if (idx >= (size_t)BB * HH) return;
    int r = (int)(idx >> 7);
    int c = (int)(idx & 127);
    float v;
    if (c < TD) v = day_table[day_ids[r] * TD + c];
    else        v = time_table[time_ids[r] * TD + (c - TD)];
    tin[idx] = v;
}

__global__ void build_comb_kernel(const int* __restrict__ orig,
                                  const int* __restrict__ dest,
                                  const int* __restrict__ mode_ids,
                                  const float* __restrict__ h,
                                  const float* __restrict__ temporal,
                                  const float* __restrict__ mode_table,
                                  float* __restrict__ comb) {
    size_t idx = (size_t)blockIdx.x * blockDim.x + threadIdx.x;
    if (idx >= (size_t)BB * PIN) return;
    int r = (int)(idx / PIN);
    int c = (int)(idx % PIN);
    float v;
    if (c < 128)       v = h[(size_t)orig[r] * HH + c];
    else if (c < 256)  v = h[(size_t)dest[r] * HH + (c - 128)];
    else if (c < 384)  v = temporal[(size_t)r * HH + (c - 256)];
    else               v = mode_table[mode_ids[r] * TD + (c - 384)];
    comb[idx] = v;
}

// ---------------- final layer ------------------------------------------------
__global__ void head_final_kernel(const float* __restrict__ z3,
                                  const float* __restrict__ Wh4,
                                  const float* __restrict__ bh4,
                                  float* __restrict__ out) {
    int gtid = blockIdx.x * blockDim.x + threadIdx.x;
    int r = gtid >> 5;
    if (r >= BB) return;
    int lane = gtid & 31;
    const float* zr = z3 + (size_t)r * 64;
    float s = zr[lane] * Wh4[lane] + zr[32 + lane] * Wh4[32 + lane];
    #pragma unroll
    for (int o = 16; o; o >>= 1) s += __shfl_xor_sync(0xFFFFFFFFu, s, o);
    if (lane == 0) {
        float v = s + bh4[0];
        out[r] = 1.0f / (1.0f + expf(-v));
    }
}

// =============================================================================
extern "C" void kernel_launch(void* const* d_in, const int* in_sizes, int n_in,
                              void* d_out, int out_size) {
    const float* x          = (const float*)d_in[0];
    const int*   edge_index = (const int*)  d_in[1];
    const int*   origin_ids = (const int*)  d_in[2];
    const int*   dest_ids   = (const int*)  d_in[3];
    const int*   day_ids    = (const int*)  d_in[4];
    const int*   time_ids   = (const int*)  d_in[5];
    const int*   mode_ids   = (const int*)  d_in[6];
    const float* W1 = (const float*)d_in[7];
    const float* b1 = (const float*)d_in[8];
    const float* W2 = (const float*)d_in[9];
    const float* b2 = (const float*)d_in[10];
    const float* W3 = (const float*)d_in[11];
    const float* b3 = (const float*)d_in[12];
    const float* day_table  = (const float*)d_in[13];
    const float* time_table = (const float*)d_in[14];
    const float* mode_table = (const float*)d_in[15];
    const float* Wf  = (const float*)d_in[16];
    const float* bf  = (const float*)d_in[17];
    const float* Wh1 = (const float*)d_in[18];
    const float* bh1 = (const float*)d_in[19];
    const float* Wh2 = (const float*)d_in[20];
    const float* bh2 = (const float*)d_in[21];
    const float* Wh3 = (const float*)d_in[22];
    const float* bh3 = (const float*)d_in[23];
    const float* Wh4 = (const float*)d_in[24];
    const float* bh4 = (const float*)d_in[25];
    float* out = (float*)d_out;

    const int* srcE = edge_index;
    const int* dstE = edge_index + EE;

    float *dinv, *hw, *h, *tin, *temp, *comb, *z1, *z2, *z3, *csr_coef;
    int *cnt, *rowp, *cursor, *bsum, *csr_src;
    cudaGetSymbolAddress((void**)&dinv, g_dinv);
    cudaGetSymbolAddress((void**)&cnt,  g_cnt);
    cudaGetSymbolAddress((void**)&rowp, g_rowp);
    cudaGetSymbolAddress((void**)&cursor, g_cursor);
    cudaGetSymbolAddress((void**)&bsum, g_bsum);
    cudaGetSymbolAddress((void**)&csr_src,  g_csr_src);
    cudaGetSymbolAddress((void**)&csr_coef, g_csr_coef);
    cudaGetSymbolAddress((void**)&hw,   g_hw);
    cudaGetSymbolAddress((void**)&h,    g_h);
    cudaGetSymbolAddress((void**)&tin,  g_tin);
    cudaGetSymbolAddress((void**)&temp, g_temp);
    cudaGetSymbolAddress((void**)&comb, g_comb);
    cudaGetSymbolAddress((void**)&z1,   g_z1);
    cudaGetSymbolAddress((void**)&z2,   g_z2);
    cudaGetSymbolAddress((void**)&z3,   g_z3);

    const int T = 256;

    // --- CSR build (once) ---
    cnt_zero_kernel<<<(NN + T - 1) / T, T>>>(cnt);
    cnt_count_kernel<<<(EE + T - 1) / T, T>>>(dstE, cnt);
    dinv_kernel<<<(NN + T - 1) / T, T>>>(cnt, dinv);
    scan_block_kernel<<<NBLK_SCAN, SCAN_B>>>(cnt, rowp, bsum);
    scan_bsum_kernel<<<1, 128>>>(bsum);
    scan_add_kernel<<<(NN + T - 1) / T, T>>>(rowp, bsum, cursor);
    scatter_kernel<<<(EE + T - 1) / T, T>>>(srcE, dstE, dinv, cursor, csr_src, csr_coef);

    dim3 blk(256);
    dim3 gNode(1, (NN + 127) / 128);
    dim3 gHead(1, (BB + 127) / 128);
    int aggBlocks = (NN * 4 + 7) / 8;   // 8 warps per 256-thread block

    // --- GCN layers ---
    tc_gemm_kernel<<<gNode, blk>>>(x, W1, nullptr, hw, NN, FF, HH, 0);
    agg_fused_kernel<<<aggBlocks, T>>>(rowp, csr_src, csr_coef, dinv, hw, b1, h);
    tc_gemm_kernel<<<gNode, blk>>>(h, W2, nullptr, hw, NN, HH, HH, 0);
    agg_fused_kernel<<<aggBlocks, T>>>(rowp, csr_src, csr_coef, dinv, hw, b2, h);
    tc_gemm_kernel<<<gNode, blk>>>(h, W3, nullptr, hw, NN, HH, HH, 0);
    agg_fused_kernel<<<aggBlocks, T>>>(rowp, csr_src, csr_coef, dinv, hw, b3, h);

    // --- temporal fusion ---
    int bhBlocks = (int)(((size_t)BB * HH + T - 1) / T);
    build_tin_kernel<<<bhBlocks, T>>>(day_ids, time_ids, day_table, time_table, tin);
    tc_gemm_kernel<<<gHead, blk>>>(tin, Wf, bf, temp, BB, HH, HH, 1);

    // --- combined features ---
    int combBlocks = (int)(((size_t)BB * PIN + T - 1) / T);
    build_comb_kernel<<<combBlocks, T>>>(origin_ids, dest_ids, mode_ids,
                                         h, temp, mode_table, comb);

    // --- prediction head ---
    dim3 gZ1(2, (BB + 127) / 128);
    tc_gemm_kernel<<<gZ1, blk>>>(comb, Wh1, bh1, z1, BB, PIN, 256, 1);
    tc_gemm_kernel<<<gHead, blk>>>(z1, Wh2, bh2, z2, BB, 256, 128, 1);
    tc_gemm_kernel<<<gHead, blk>>>(z2, Wh3, bh3, z3, BB, 128, 64, 1);

    head_final_kernel<<<(int)(((size_t)BB * 32 + T - 1) / T), T>>>(z3, Wh4, bh4, out);
}

// round 5
// speedup vs baseline: 4.8476x; 1.5762x over previous
#include <cuda_runtime.h>
#include <cuda_bf16.h>
#include <math.h>
#include <cstdint>

// Problem constants
#define NN 100000      // nodes
#define FF 128         // node features
#define HH 128         // hidden
#define EE 1600000     // edges
#define BB 65536       // queries
#define TD 64          // H/2
#define PIN 448        // 2H + H + TD

#define SCAN_B 1024
#define NBLK_SCAN ((NN + SCAN_B - 1) / SCAN_B)   // 98

// ---------------- scratch (static device memory; no allocation) --------------
__device__ float g_dinv[NN];
__device__ int   g_cnt  [NN];
__device__ int   g_rowp [NN + 1];
__device__ int   g_cursor[NN];
__device__ int   g_bsum [NBLK_SCAN + 1];
__device__ int   g_csr_src [EE];
__device__ float g_csr_coef[EE];
__device__ __nv_bfloat16 g_hw  [(size_t)NN * HH];
__device__ __nv_bfloat16 g_h   [(size_t)NN * HH];
__device__ __nv_bfloat16 g_temp[(size_t)BB * HH];
__device__ __nv_bfloat16 g_z1  [(size_t)BB * 256];
__device__ __nv_bfloat16 g_z2  [(size_t)BB * 128];
__device__ __nv_bfloat16 g_z3  [(size_t)BB * 64];

// ======================= HMMA helpers ========================================
__device__ __forceinline__ uint32_t smem_to_u32(const void* p) {
    uint32_t a;
    asm("{ .reg .u64 t; cvta.to.shared.u64 t, %1; cvt.u32.u64 %0, t; }"
        : "=r"(a) : "l"(p));
    return a;
}
__device__ __forceinline__ void ldm_x4(uint32_t& r0, uint32_t& r1,
                                       uint32_t& r2, uint32_t& r3, uint32_t addr) {
    asm volatile("ldmatrix.sync.aligned.m8n8.x4.shared.b16 {%0,%1,%2,%3}, [%4];"
        : "=r"(r0), "=r"(r1), "=r"(r2), "=r"(r3) : "r"(addr));
}
__device__ __forceinline__ void mma_bf16(float* c, const uint32_t* a,
                                         uint32_t b0, uint32_t b1) {
    asm volatile(
        "mma.sync.aligned.m16n8k16.row.col.f32.bf16.bf16.f32 "
        "{%0,%1,%2,%3}, {%4,%5,%6,%7}, {%8,%9}, {%0,%1,%2,%3};"
        : "+f"(c[0]), "+f"(c[1]), "+f"(c[2]), "+f"(c[3])
        : "r"(a[0]), "r"(a[1]), "r"(a[2]), "r"(a[3]), "r"(b0), "r"(b1));
}

// ======================= tensor-core GEMM ====================================
// C[M, Ntot] = A[M, K] @ W[K, Ntot]   (bf16 mma, fp32 accumulate, bf16 out)
// ASRC: 0 = fp32 dense, 1 = bf16 dense, 2 = head1 gather (K=448), 3 = tin gather
// mode 0: C = v      mode 1: C = relu(v + bias)
#define LDBYTES 144

struct GParams {
    const void* A;                        // dense A (fp32 or bf16)
    const __nv_bfloat16* h;               // gathered route features
    const __nv_bfloat16* temp;            // temporal activations
    const float* day_table; const float* time_table; const float* mode_table;
    const int* orig; const int* dest; const int* day_ids; const int* time_ids;
    const int* mode_ids;
};

template<int ASRC>
__global__ void __launch_bounds__(256, 2)
tc_gemm_kernel(GParams P, const float* __restrict__ W,
               const float* __restrict__ bias, __nv_bfloat16* __restrict__ C,
               int M, int K, int Ntot, int mode) {
    __shared__ __align__(16) char smem[2 * 128 * LDBYTES];
    char* sA = smem;
    char* sB = smem + 128 * LDBYTES;
    uint32_t sAu = smem_to_u32(sA);
    uint32_t sBu = smem_to_u32(sB);

    int tid = threadIdx.x;
    int wid = tid >> 5;
    int lane = tid & 31;
    int wm = wid >> 1;
    int wn = wid & 1;

    int rowBase = blockIdx.y * 128;
    int colBase = blockIdx.x * 128;

    float acc[2][8][4];
    #pragma unroll
    for (int mt = 0; mt < 2; mt++)
        #pragma unroll
        for (int nf = 0; nf < 8; nf++)
            #pragma unroll
            for (int j = 0; j < 4; j++) acc[mt][nf][j] = 0.0f;

    int lq = lane & 15;
    int lh = lane >> 4;

    for (int k0 = 0; k0 < K; k0 += 64) {
        __syncthreads();
        // ---- A tile staging: 128 rows x 64 bf16 ----
        if (ASRC == 0) {
            const float* A = (const float*)P.A;
            #pragma unroll 4
            for (int i = tid; i < 128 * 32; i += 256) {
                int r = i >> 5, kp = i & 31;
                int gr = rowBase + r;
                float2 v = make_float2(0.f, 0.f);
                if (gr < M) v = *(const float2*)(A + (size_t)gr * K + k0 + 2 * kp);
                *(__nv_bfloat162*)(sA + r * LDBYTES + kp * 4) = __float22bfloat162_rn(v);
            }
        } else if (ASRC == 1) {
            const __nv_bfloat16* A = (const __nv_bfloat16*)P.A;
            #pragma unroll 4
            for (int i = tid; i < 128 * 8; i += 256) {     // 16B chunks
                int r = i >> 3, seg = i & 7;
                int gr = rowBase + r;
                uint4 v = make_uint4(0, 0, 0, 0);
                if (gr < M) v = *(const uint4*)(A + (size_t)gr * K + k0 + seg * 8);
                *(uint4*)(sA + r * LDBYTES + seg * 16) = v;
            }
        } else if (ASRC == 2) {
            // head1: K=448, regions [0,128)=h[orig], [128,256)=h[dest],
            // [256,384)=temp, [384,448)=mode_table (fp32, 64 wide)
            if (k0 < 384) {
                #pragma unroll 4
                for (int i = tid; i < 128 * 8; i += 256) {
                    int r = i >> 3, seg = i & 7;
                    int gr = rowBase + r;
                    const __nv_bfloat16* srcp;
                    if (k0 < 128)       srcp = P.h + (size_t)P.orig[gr] * HH + k0;
                    else if (k0 < 256)  srcp = P.h + (size_t)P.dest[gr] * HH + (k0 - 128);
                    else                srcp = P.temp + (size_t)gr * HH + (k0 - 256);
                    *(uint4*)(sA + r * LDBYTES + seg * 16) = *(const uint4*)(srcp + seg * 8);
                }
            } else {
                #pragma unroll 4
                for (int i = tid; i < 128 * 32; i += 256) {
                    int r = i >> 5, kp = i & 31;
                    int gr = rowBase + r;
                    const float* srcp = P.mode_table + (size_t)P.mode_ids[gr] * TD;
                    float2 v = *(const float2*)(srcp + 2 * kp);
                    *(__nv_bfloat162*)(sA + r * LDBYTES + kp * 4) = __float22bfloat162_rn(v);
                }
            }
        } else {
            // tin: K=128, [0,64)=day_table[day_ids], [64,128)=time_table[time_ids]
            #pragma unroll 4
            for (int i = tid; i < 128 * 32; i += 256) {
                int r = i >> 5, kp = i & 31;
                int gr = rowBase + r;
                const float* srcp = (k0 == 0)
                    ? P.day_table  + (size_t)P.day_ids[gr]  * TD
                    : P.time_table + (size_t)P.time_ids[gr] * TD;
                float2 v = *(const float2*)(srcp + 2 * kp);
                *(__nv_bfloat162*)(sA + r * LDBYTES + kp * 4) = __float22bfloat162_rn(v);
            }
        }
        // ---- B tile: Bs[n][k] = W[k0+k][colBase+n] ----
        #pragma unroll 4
        for (int i = tid; i < 64 * 128; i += 256) {
            int n = i & 127, kk = i >> 7;
            int gc = colBase + n;
            float v = (gc < Ntot) ? W[(size_t)(k0 + kk) * Ntot + gc] : 0.0f;
            *(__nv_bfloat16*)(sB + n * LDBYTES + kk * 2) = __float2bfloat16(v);
        }
        __syncthreads();

        #pragma unroll
        for (int ks = 0; ks < 4; ks++) {
            uint32_t af[2][4];
            #pragma unroll
            for (int mt = 0; mt < 2; mt++) {
                uint32_t addr = sAu + (uint32_t)(wm * 32 + mt * 16 + lq) * LDBYTES
                              + ks * 32 + lh * 16;
                ldm_x4(af[mt][0], af[mt][1], af[mt][2], af[mt][3], addr);
            }
            uint32_t bfr[8][2];
            #pragma unroll
            for (int g = 0; g < 4; g++) {
                uint32_t r0, r1, r2, r3;
                uint32_t addr = sBu + (uint32_t)(wn * 64 + g * 16 + lq) * LDBYTES
                              + ks * 32 + lh * 16;
                ldm_x4(r0, r1, r2, r3, addr);
                bfr[2 * g][0] = r0;     bfr[2 * g][1] = r2;
                bfr[2 * g + 1][0] = r1; bfr[2 * g + 1][1] = r3;
            }
            #pragma unroll
            for (int mt = 0; mt < 2; mt++)
                #pragma unroll
                for (int nf = 0; nf < 8; nf++)
                    mma_bf16(acc[mt][nf], af[mt], bfr[nf][0], bfr[nf][1]);
        }
    }

    int rowOff = lane >> 2;
    int colOff = (lane & 3) * 2;
    #pragma unroll
    for (int mt = 0; mt < 2; mt++) {
        #pragma unroll
        for (int half = 0; half < 2; half++) {
            int r = rowBase + wm * 32 + mt * 16 + rowOff + half * 8;
            if (r >= M) continue;
            #pragma unroll
            for (int nf = 0; nf < 8; nf++) {
                int c = colBase + wn * 64 + nf * 8 + colOff;
                if (c >= Ntot) continue;
                float v0 = acc[mt][nf][half * 2 + 0];
                float v1 = acc[mt][nf][half * 2 + 1];
                if (mode == 1) {
                    v0 = fmaxf(v0 + bias[c], 0.f);
                    v1 = fmaxf(v1 + bias[c + 1], 0.f);
                }
                *(__nv_bfloat162*)(C + (size_t)r * Ntot + c) =
                    __float22bfloat162_rn(make_float2(v0, v1));
            }
        }
    }
}

// ======================= CSR build ===========================================
__global__ void cnt_zero_kernel(int* cnt) {
    int i = blockIdx.x * blockDim.x + threadIdx.x;
    if (i < NN) cnt[i] = 0;
}
__global__ void cnt_count_kernel(const int* __restrict__ dst, int* cnt) {
    int e = blockIdx.x * blockDim.x + threadIdx.x;
    if (e < EE) atomicAdd(&cnt[dst[e]], 1);
}
__global__ void dinv_kernel(const int* __restrict__ cnt, float* dinv) {
    int i = blockIdx.x * blockDim.x + threadIdx.x;
    if (i < NN) dinv[i] = rsqrtf((float)cnt[i] + 1.0f);
}
__global__ void scan_block_kernel(const int* __restrict__ cnt, int* excl, int* bsum) {
    __shared__ int s[SCAN_B];
    int tid = threadIdx.x;
    int i = blockIdx.x * SCAN_B + tid;
    int v = (i < NN) ? cnt[i] : 0;
    s[tid] = v;
    __syncthreads();
    for (int off = 1; off < SCAN_B; off <<= 1) {
        int t = (tid >= off) ? s[tid - off] : 0;
        __syncthreads();
        s[tid] += t;
        __syncthreads();
    }
    if (i < NN) excl[i] = s[tid] - v;
    if (tid == SCAN_B - 1) bsum[blockIdx.x] = s[tid];
}
__global__ void scan_bsum_kernel(int* bsum) {
    __shared__ int s[NBLK_SCAN];
    int tid = threadIdx.x;
    if (tid < NBLK_SCAN) s[tid] = bsum[tid];
    __syncthreads();
    if (tid == 0) {
        int run = 0;
        for (int b = 0; b < NBLK_SCAN; b++) { int t = s[b]; s[b] = run; run += t; }
    }
    __syncthreads();
    if (tid < NBLK_SCAN) bsum[tid] = s[tid];
}
__global__ void scan_add_kernel(int* rowp, const int* __restrict__ bsum, int* cursor) {
    int i = blockIdx.x * blockDim.x + threadIdx.x;
    if (i < NN) {
        int v = rowp[i] + bsum[i / SCAN_B];
        rowp[i] = v;
        cursor[i] = v;
    }
    if (i == 0) rowp[NN] = EE;
}
__global__ void scatter_kernel(const int* __restrict__ src, const int* __restrict__ dst,
                               const float* __restrict__ dinv,
                               int* cursor, int* csr_src, float* csr_coef) {
    int e = blockIdx.x * blockDim.x + threadIdx.x;
    if (e >= EE) return;
    int s = src[e], d = dst[e];
    int p = atomicAdd(&cursor[d], 1);
    csr_src[p] = s;
    csr_coef[p] = dinv[s] * dinv[d];
}

// ============== fused aggregation: h = relu(D^-1/2 (A+I) D^-1/2 hw + b) ======
// one warp per (node, 64-col group); lane handles 2 cols via bf16x2
__global__ void __launch_bounds__(256)
agg_fused_kernel(const int* __restrict__ rowp,
                 const int* __restrict__ csr_src,
                 const float* __restrict__ csr_coef,
                 const float* __restrict__ dinv,
                 const __nv_bfloat16* __restrict__ hw,
                 const float* __restrict__ bias,
                 __nv_bfloat16* __restrict__ h) {
    int gw = (blockIdx.x * blockDim.x + threadIdx.x) >> 5;
    int node = gw >> 1;
    if (node >= NN) return;
    int grp = gw & 1;
    int lane = threadIdx.x & 31;
    int col = grp * 64 + lane * 2;

    int beg = rowp[node], end = rowp[node + 1];
    float s0 = 0.0f, s1 = 0.0f;
    for (int i = beg; i < end; i += 32) {
        int n = end - i; if (n > 32) n = 32;
        int sidx = 0; float cf = 0.0f;
        if (lane < n) { sidx = csr_src[i + lane]; cf = csr_coef[i + lane]; }
        #pragma unroll 4
        for (int j = 0; j < n; j++) {
            int s   = __shfl_sync(0xFFFFFFFFu, sidx, j);
            float c = __shfl_sync(0xFFFFFFFFu, cf, j);
            __nv_bfloat162 v = *(const __nv_bfloat162*)(hw + (size_t)s * HH + col);
            float2 f = __bfloat1622float2(v);
            s0 = fmaf(f.x, c, s0);
            s1 = fmaf(f.y, c, s1);
        }
    }
    float di = dinv[node];
    float di2 = di * di;
    __nv_bfloat162 vs = *(const __nv_bfloat162*)(hw + (size_t)node * HH + col);
    float2 fs = __bfloat1622float2(vs);
    s0 = fmaf(fs.x, di2, s0);
    s1 = fmaf(fs.y, di2, s1);
    s0 = fmaxf(s0 + bias[col], 0.0f);
    s1 = fmaxf(s1 + bias[col + 1], 0.0f);
    *(__nv_bfloat162*)(h + (size_t)node * HH + col) =
        __float22bfloat162_rn(make_float2(s0, s1));
}

// ---------------- final layer ------------------------------------------------
__global__ void head_final_kernel(const __nv_bfloat16* __restrict__ z3,
                                  const float* __restrict__ Wh4,
                                  const float* __restrict__ bh4,
                                  float* __restrict__ out) {
    int gtid = blockIdx.x * blockDim.x + threadIdx.x;
    int r = gtid >> 5;
    if (r >= BB) return;
    int lane = gtid & 31;
    const __nv_bfloat16* zr = z3 + (size_t)r * 64;
    float s = __bfloat162float(zr[lane]) * Wh4[lane]
            + __bfloat162float(zr[32 + lane]) * Wh4[32 + lane];
    #pragma unroll
    for (int o = 16; o; o >>= 1) s += __shfl_xor_sync(0xFFFFFFFFu, s, o);
    if (lane == 0) {
        float v = s + bh4[0];
        out[r] = 1.0f / (1.0f + expf(-v));
    }
}

// =============================================================================
extern "C" void kernel_launch(void* const* d_in, const int* in_sizes, int n_in,
                              void* d_out, int out_size) {
    const float* x          = (const float*)d_in[0];
    const int*   edge_index = (const int*)  d_in[1];
    const int*   origin_ids = (const int*)  d_in[2];
    const int*   dest_ids   = (const int*)  d_in[3];
    const int*   day_ids    = (const int*)  d_in[4];
    const int*   time_ids   = (const int*)  d_in[5];
    const int*   mode_ids   = (const int*)  d_in[6];
    const float* W1 = (const float*)d_in[7];
    const float* b1 = (const float*)d_in[8];
    const float* W2 = (const float*)d_in[9];
    const float* b2 = (const float*)d_in[10];
    const float* W3 = (const float*)d_in[11];
    const float* b3 = (const float*)d_in[12];
    const float* day_table  = (const float*)d_in[13];
    const float* time_table = (const float*)d_in[14];
    const float* mode_table = (const float*)d_in[15];
    const float* Wf  = (const float*)d_in[16];
    const float* bf  = (const float*)d_in[17];
    const float* Wh1 = (const float*)d_in[18];
    const float* bh1 = (const float*)d_in[19];
    const float* Wh2 = (const float*)d_in[20];
    const float* bh2 = (const float*)d_in[21];
    const float* Wh3 = (const float*)d_in[22];
    const float* bh3 = (const float*)d_in[23];
    const float* Wh4 = (const float*)d_in[24];
    const float* bh4 = (const float*)d_in[25];
    float* out = (float*)d_out;

    const int* srcE = edge_index;
    const int* dstE = edge_index + EE;

    float *dinv, *csr_coef;
    int *cnt, *rowp, *cursor, *bsum, *csr_src;
    __nv_bfloat16 *hw, *h, *temp, *z1, *z2, *z3;
    cudaGetSymbolAddress((void**)&dinv, g_dinv);
    cudaGetSymbolAddress((void**)&cnt,  g_cnt);
    cudaGetSymbolAddress((void**)&rowp, g_rowp);
    cudaGetSymbolAddress((void**)&cursor, g_cursor);
    cudaGetSymbolAddress((void**)&bsum, g_bsum);
    cudaGetSymbolAddress((void**)&csr_src,  g_csr_src);
    cudaGetSymbolAddress((void**)&csr_coef, g_csr_coef);
    cudaGetSymbolAddress((void**)&hw,   g_hw);
    cudaGetSymbolAddress((void**)&h,    g_h);
    cudaGetSymbolAddress((void**)&temp, g_temp);
    cudaGetSymbolAddress((void**)&z1,   g_z1);
    cudaGetSymbolAddress((void**)&z2,   g_z2);
    cudaGetSymbolAddress((void**)&z3,   g_z3);

    const int T = 256;

    // --- CSR build (once) ---
    cnt_zero_kernel<<<(NN + T - 1) / T, T>>>(cnt);
    cnt_count_kernel<<<(EE + T - 1) / T, T>>>(dstE, cnt);
    dinv_kernel<<<(NN + T - 1) / T, T>>>(cnt, dinv);
    scan_block_kernel<<<NBLK_SCAN, SCAN_B>>>(cnt, rowp, bsum);
    scan_bsum_kernel<<<1, 128>>>(bsum);
    scan_add_kernel<<<(NN + T - 1) / T, T>>>(rowp, bsum, cursor);
    scatter_kernel<<<(EE + T - 1) / T, T>>>(srcE, dstE, dinv, cursor, csr_src, csr_coef);

    dim3 blk(256);
    dim3 gNode(1, (NN + 127) / 128);
    dim3 gHead(1, (BB + 127) / 128);
    int aggBlocks = (NN * 2 + 7) / 8;

    GParams P = {};
    P.h = h; P.temp = temp;
    P.day_table = day_table; P.time_table = time_table; P.mode_table = mode_table;
    P.orig = origin_ids; P.dest = dest_ids;
    P.day_ids = day_ids; P.time_ids = time_ids; P.mode_ids = mode_ids;

    // --- GCN layers ---
    GParams Pa = P; Pa.A = x;
    tc_gemm_kernel<0><<<gNode, blk>>>(Pa, W1, nullptr, hw, NN, FF, HH, 0);
    agg_fused_kernel<<<aggBlocks, T>>>(rowp, csr_src, csr_coef, dinv, hw, b1, h);
    Pa.A = h;
    tc_gemm_kernel<1><<<gNode, blk>>>(Pa, W2, nullptr, hw, NN, HH, HH, 0);
    agg_fused_kernel<<<aggBlocks, T>>>(rowp, csr_src, csr_coef, dinv, hw, b2, h);
    tc_gemm_kernel<1><<<gNode, blk>>>(Pa, W3, nullptr, hw, NN, HH, HH, 0);
    agg_fused_kernel<<<aggBlocks, T>>>(rowp, csr_src, csr_coef, dinv, hw, b3, h);

    // --- temporal fusion (gathered staging) ---
    tc_gemm_kernel<3><<<gHead, blk>>>(P, Wf, bf, temp, BB, HH, HH, 1);

    // --- prediction head (Wh1 gathers comb on the fly) ---
    dim3 gZ1(2, (BB + 127) / 128);
    tc_gemm_kernel<2><<<gZ1, blk>>>(P, Wh1, bh1, z1, BB, PIN, 256, 1);
    GParams Pz = P; Pz.A = z1;
    tc_gemm_kernel<1><<<gHead, blk>>>(Pz, Wh2, bh2, z2, BB, 256, 128, 1);
    Pz.A = z2;
    tc_gemm_kernel<1><<<gHead, blk>>>(Pz, Wh3, bh3, z3, BB, 128, 64, 1);

    head_final_kernel<<<(int)(((size_t)BB * 32 + T - 1) / T), T>>>(z3, Wh4, bh4, out);
}

// round 6
// speedup vs baseline: 7.8372x; 1.6167x over previous
#include <cuda_runtime.h>
#include <cuda_bf16.h>
#include <math.h>
#include <cstdint>

// Problem constants
#define NN 100000      // nodes
#define FF 128         // node features
#define HH 128         // hidden
#define EE 1600000     // edges
#define BB 65536       // queries
#define TD 64          // H/2
#define PIN 448        // 2H + H + TD

#define SCAN_B 1024
#define NBLK_SCAN ((NN + SCAN_B - 1) / SCAN_B)   // 98

// bf16 transposed-weight pool offsets (Wt[n][k], row stride = K)
#define OFF_W1  0
#define OFF_W2  16384
#define OFF_W3  32768
#define OFF_WF  49152
#define OFF_WH1 65536          // 256 rows x 448
#define OFF_WH2 180224         // 128 rows x 256
#define OFF_WH3 212992         // 64 rows x 128
#define WT_TOTAL 221184

// ---------------- scratch (static device memory; no allocation) --------------
__device__ float g_dinv[NN];
__device__ int   g_cnt  [NN];
__device__ int   g_rowp [NN + 1];
__device__ int   g_cursor[NN];
__device__ int   g_bsum [NBLK_SCAN + 1];
__device__ int   g_csr_src [EE];
__device__ float g_csr_coef[EE];
__device__ __nv_bfloat16 g_wt  [WT_TOTAL];
__device__ __nv_bfloat16 g_hw  [(size_t)NN * HH];
__device__ __nv_bfloat16 g_h   [(size_t)NN * HH];
__device__ __nv_bfloat16 g_temp[(size_t)BB * HH];
__device__ __nv_bfloat16 g_z1  [(size_t)BB * 256];
__device__ __nv_bfloat16 g_z2  [(size_t)BB * 128];
__device__ __nv_bfloat16 g_z3  [(size_t)BB * 64];

// ======================= HMMA helpers ========================================
__device__ __forceinline__ uint32_t smem_to_u32(const void* p) {
    uint32_t a;
    asm("{ .reg .u64 t; cvta.to.shared.u64 t, %1; cvt.u32.u64 %0, t; }"
        : "=r"(a) : "l"(p));
    return a;
}
__device__ __forceinline__ void ldm_x4(uint32_t& r0, uint32_t& r1,
                                       uint32_t& r2, uint32_t& r3, uint32_t addr) {
    asm volatile("ldmatrix.sync.aligned.m8n8.x4.shared.b16 {%0,%1,%2,%3}, [%4];"
        : "=r"(r0), "=r"(r1), "=r"(r2), "=r"(r3) : "r"(addr));
}
__device__ __forceinline__ void mma_bf16(float* c, const uint32_t* a,
                                         uint32_t b0, uint32_t b1) {
    asm volatile(
        "mma.sync.aligned.m16n8k16.row.col.f32.bf16.bf16.f32 "
        "{%0,%1,%2,%3}, {%4,%5,%6,%7}, {%8,%9}, {%0,%1,%2,%3};"
        : "+f"(c[0]), "+f"(c[1]), "+f"(c[2]), "+f"(c[3])
        : "r"(a[0]), "r"(a[1]), "r"(a[2]), "r"(a[3]), "r"(b0), "r"(b1));
}

// ============ weight transpose + bf16 convert (once per launch) ==============
struct WtSeg { const float* src; int K; int N; int off; };
struct WtParams { WtSeg seg[7]; };

__global__ void wt_build_kernel(WtParams P, __nv_bfloat16* wt) {
    int idx = blockIdx.x * blockDim.x + threadIdx.x;
    if (idx >= WT_TOTAL) return;
    #pragma unroll
    for (int s = 0; s < 7; s++) {
        int sz = P.seg[s].K * P.seg[s].N;
        if (idx < P.seg[s].off + sz) {
            int li = idx - P.seg[s].off;
            int K = P.seg[s].K;
            int n = li / K, k = li - n * K;
            wt[idx] = __float2bfloat16(P.seg[s].src[(size_t)k * P.seg[s].N + n]);
            return;
        }
    }
}

// ======================= tensor-core GEMM ====================================
// C[M, Ntot] = A[M, K] @ W[K, Ntot]; Wt is bf16 transposed: Wt[n][k], stride K.
// ASRC: 0 = fp32 dense, 1 = bf16 dense, 2 = head1 gather (K=448), 3 = tin gather
// mode 0: C = v      mode 1: C = relu(v + bias)
#define LDBYTES 144

struct GParams {
    const void* A;
    const __nv_bfloat16* h;
    const __nv_bfloat16* temp;
    const float* day_table; const float* time_table; const float* mode_table;
    const int* orig; const int* dest; const int* day_ids; const int* time_ids;
    const int* mode_ids;
};

template<int ASRC>
__global__ void __launch_bounds__(256, 2)
tc_gemm_kernel(GParams P, const __nv_bfloat16* __restrict__ Wt,
               const float* __restrict__ bias, __nv_bfloat16* __restrict__ C,
               int M, int K, int Ntot, int mode) {
    __shared__ __align__(16) char smem[2 * 128 * LDBYTES];
    char* sA = smem;
    char* sB = smem + 128 * LDBYTES;
    uint32_t sAu = smem_to_u32(sA);
    uint32_t sBu = smem_to_u32(sB);

    int tid = threadIdx.x;
    int wid = tid >> 5;
    int lane = tid & 31;
    int wm = wid >> 1;
    int wn = wid & 1;

    int rowBase = blockIdx.y * 128;
    int colBase = blockIdx.x * 128;

    float acc[2][8][4];
    #pragma unroll
    for (int mt = 0; mt < 2; mt++)
        #pragma unroll
        for (int nf = 0; nf < 8; nf++)
            #pragma unroll
            for (int j = 0; j < 4; j++) acc[mt][nf][j] = 0.0f;

    int lq = lane & 15;
    int lh = lane >> 4;

    for (int k0 = 0; k0 < K; k0 += 64) {
        __syncthreads();
        // ---- A tile staging: 128 rows x 64 bf16 ----
        if (ASRC == 0) {
            const float* A = (const float*)P.A;
            #pragma unroll 4
            for (int i = tid; i < 128 * 32; i += 256) {
                int r = i >> 5, kp = i & 31;
                int gr = rowBase + r;
                float2 v = make_float2(0.f, 0.f);
                if (gr < M) v = *(const float2*)(A + (size_t)gr * K + k0 + 2 * kp);
                *(__nv_bfloat162*)(sA + r * LDBYTES + kp * 4) = __float22bfloat162_rn(v);
            }
        } else if (ASRC == 1) {
            const __nv_bfloat16* A = (const __nv_bfloat16*)P.A;
            #pragma unroll 4
            for (int i = tid; i < 128 * 8; i += 256) {
                int r = i >> 3, seg = i & 7;
                int gr = rowBase + r;
                uint4 v = make_uint4(0, 0, 0, 0);
                if (gr < M) v = *(const uint4*)(A + (size_t)gr * K + k0 + seg * 8);
                *(uint4*)(sA + r * LDBYTES + seg * 16) = v;
            }
        } else if (ASRC == 2) {
            if (k0 < 384) {
                #pragma unroll 4
                for (int i = tid; i < 128 * 8; i += 256) {
                    int r = i >> 3, seg = i & 7;
                    int gr = rowBase + r;
                    const __nv_bfloat16* srcp;
                    if (k0 < 128)       srcp = P.h + (size_t)P.orig[gr] * HH + k0;
                    else if (k0 < 256)  srcp = P.h + (size_t)P.dest[gr] * HH + (k0 - 128);
                    else                srcp = P.temp + (size_t)gr * HH + (k0 - 256);
                    *(uint4*)(sA + r * LDBYTES + seg * 16) = *(const uint4*)(srcp + seg * 8);
                }
            } else {
                #pragma unroll 4
                for (int i = tid; i < 128 * 32; i += 256) {
                    int r = i >> 5, kp = i & 31;
                    int gr = rowBase + r;
                    const float* srcp = P.mode_table + (size_t)P.mode_ids[gr] * TD;
                    float2 v = *(const float2*)(srcp + 2 * kp);
                    *(__nv_bfloat162*)(sA + r * LDBYTES + kp * 4) = __float22bfloat162_rn(v);
                }
            }
        } else {
            #pragma unroll 4
            for (int i = tid; i < 128 * 32; i += 256) {
                int r = i >> 5, kp = i & 31;
                int gr = rowBase + r;
                const float* srcp = (k0 == 0)
                    ? P.day_table  + (size_t)P.day_ids[gr]  * TD
                    : P.time_table + (size_t)P.time_ids[gr] * TD;
                float2 v = *(const float2*)(srcp + 2 * kp);
                *(__nv_bfloat162*)(sA + r * LDBYTES + kp * 4) = __float22bfloat162_rn(v);
            }
        }
        // ---- B tile: 128 n-rows x 64 bf16 from transposed bf16 weights ----
        #pragma unroll 4
        for (int i = tid; i < 128 * 8; i += 256) {
            int n = i >> 3, seg = i & 7;
            int gc = colBase + n;
            uint4 v = make_uint4(0, 0, 0, 0);
            if (gc < Ntot) v = *(const uint4*)(Wt + (size_t)gc * K + k0 + seg * 8);
            *(uint4*)(sB + n * LDBYTES + seg * 16) = v;
        }
        __syncthreads();

        #pragma unroll
        for (int ks = 0; ks < 4; ks++) {
            uint32_t af[2][4];
            #pragma unroll
            for (int mt = 0; mt < 2; mt++) {
                uint32_t addr = sAu + (uint32_t)(wm * 32 + mt * 16 + lq) * LDBYTES
                              + ks * 32 + lh * 16;
                ldm_x4(af[mt][0], af[mt][1], af[mt][2], af[mt][3], addr);
            }
            uint32_t bfr[8][2];
            #pragma unroll
            for (int g = 0; g < 4; g++) {
                uint32_t r0, r1, r2, r3;
                uint32_t addr = sBu + (uint32_t)(wn * 64 + g * 16 + lq) * LDBYTES
                              + ks * 32 + lh * 16;
                ldm_x4(r0, r1, r2, r3, addr);
                bfr[2 * g][0] = r0;     bfr[2 * g][1] = r2;
                bfr[2 * g + 1][0] = r1; bfr[2 * g + 1][1] = r3;
            }
            #pragma unroll
            for (int mt = 0; mt < 2; mt++)
                #pragma unroll
                for (int nf = 0; nf < 8; nf++)
                    mma_bf16(acc[mt][nf], af[mt], bfr[nf][0], bfr[nf][1]);
        }
    }

    int rowOff = lane >> 2;
    int colOff = (lane & 3) * 2;
    #pragma unroll
    for (int mt = 0; mt < 2; mt++) {
        #pragma unroll
        for (int half = 0; half < 2; half++) {
            int r = rowBase + wm * 32 + mt * 16 + rowOff + half * 8;
            if (r >= M) continue;
            #pragma unroll
            for (int nf = 0; nf < 8; nf++) {
                int c = colBase + wn * 64 + nf * 8 + colOff;
                if (c >= Ntot) continue;
                float v0 = acc[mt][nf][half * 2 + 0];
                float v1 = acc[mt][nf][half * 2 + 1];
                if (mode == 1) {
                    v0 = fmaxf(v0 + bias[c], 0.f);
                    v1 = fmaxf(v1 + bias[c + 1], 0.f);
                }
                *(__nv_bfloat162*)(C + (size_t)r * Ntot + c) =
                    __float22bfloat162_rn(make_float2(v0, v1));
            }
        }
    }
}

// ======================= CSR build ===========================================
__global__ void cnt_count_kernel(const int* __restrict__ dst, int* cnt) {
    int i = blockIdx.x * blockDim.x + threadIdx.x;
    int e = i * 4;
    if (e + 3 < EE) {
        int4 d = *(const int4*)(dst + e);
        atomicAdd(&cnt[d.x], 1);
        atomicAdd(&cnt[d.y], 1);
        atomicAdd(&cnt[d.z], 1);
        atomicAdd(&cnt[d.w], 1);
    } else {
        for (int k = e; k < EE; k++) atomicAdd(&cnt[dst[k]], 1);
    }
}
__global__ void dinv_kernel(const int* __restrict__ cnt, float* dinv) {
    int i = blockIdx.x * blockDim.x + threadIdx.x;
    if (i < NN) dinv[i] = rsqrtf((float)cnt[i] + 1.0f);
}
__global__ void scan_block_kernel(const int* __restrict__ cnt, int* excl, int* bsum) {
    __shared__ int s[SCAN_B];
    int tid = threadIdx.x;
    int i = blockIdx.x * SCAN_B + tid;
    int v = (i < NN) ? cnt[i] : 0;
    s[tid] = v;
    __syncthreads();
    for (int off = 1; off < SCAN_B; off <<= 1) {
        int t = (tid >= off) ? s[tid - off] : 0;
        __syncthreads();
        s[tid] += t;
        __syncthreads();
    }
    if (i < NN) excl[i] = s[tid] - v;
    if (tid == SCAN_B - 1) bsum[blockIdx.x] = s[tid];
}
__global__ void scan_bsum_kernel(int* bsum) {
    __shared__ int s[NBLK_SCAN];
    int tid = threadIdx.x;
    if (tid < NBLK_SCAN) s[tid] = bsum[tid];
    __syncthreads();
    if (tid == 0) {
        int run = 0;
        for (int b = 0; b < NBLK_SCAN; b++) { int t = s[b]; s[b] = run; run += t; }
    }
    __syncthreads();
    if (tid < NBLK_SCAN) bsum[tid] = s[tid];
}
__global__ void scan_add_kernel(int* rowp, const int* __restrict__ bsum, int* cursor) {
    int i = blockIdx.x * blockDim.x + threadIdx.x;
    if (i < NN) {
        int v = rowp[i] + bsum[i / SCAN_B];
        rowp[i] = v;
        cursor[i] = v;
    }
    if (i == 0) rowp[NN] = EE;
}
__global__ void scatter_kernel(const int* __restrict__ src, const int* __restrict__ dst,
                               const float* __restrict__ dinv,
                               int* cursor, int* csr_src, float* csr_coef) {
    int e = blockIdx.x * blockDim.x + threadIdx.x;
    if (e >= EE) return;
    int s = src[e], d = dst[e];
    int p = atomicAdd(&cursor[d], 1);
    csr_src[p] = s;
    csr_coef[p] = dinv[s] * dinv[d];
}

// ============== fused aggregation: h = relu(D^-1/2 (A+I) D^-1/2 hw + b) ======
// one warp per node; lane owns 4 cols (one 8B load per edge)
__global__ void __launch_bounds__(256)
agg_fused_kernel(const int* __restrict__ rowp,
                 const int* __restrict__ csr_src,
                 const float* __restrict__ csr_coef,
                 const float* __restrict__ dinv,
                 const __nv_bfloat16* __restrict__ hw,
                 const float* __restrict__ bias,
                 __nv_bfloat16* __restrict__ h) {
    int node = (blockIdx.x * blockDim.x + threadIdx.x) >> 5;
    if (node >= NN) return;
    int lane = threadIdx.x & 31;
    int col = lane * 4;

    int beg = rowp[node], end = rowp[node + 1];
    float a0 = 0.f, a1 = 0.f, a2 = 0.f, a3 = 0.f;
    for (int i = beg; i < end; i += 32) {
        int n = end - i; if (n > 32) n = 32;
        int sidx = 0; float cf = 0.0f;
        if (lane < n) { sidx = csr_src[i + lane]; cf = csr_coef[i + lane]; }
        #pragma unroll 4
        for (int j = 0; j < n; j++) {
            int s   = __shfl_sync(0xFFFFFFFFu, sidx, j);
            float c = __shfl_sync(0xFFFFFFFFu, cf, j);
            uint2 raw = *(const uint2*)(hw + (size_t)s * HH + col);
            float2 f0 = __bfloat1622float2(*(__nv_bfloat162*)&raw.x);
            float2 f1 = __bfloat1622float2(*(__nv_bfloat162*)&raw.y);
            a0 = fmaf(f0.x, c, a0);
            a1 = fmaf(f0.y, c, a1);
            a2 = fmaf(f1.x, c, a2);
            a3 = fmaf(f1.y, c, a3);
        }
    }
    float di = dinv[node];
    float di2 = di * di;
    uint2 raws = *(const uint2*)(hw + (size_t)node * HH + col);
    float2 fs0 = __bfloat1622float2(*(__nv_bfloat162*)&raws.x);
    float2 fs1 = __bfloat1622float2(*(__nv_bfloat162*)&raws.y);
    a0 = fmaf(fs0.x, di2, a0);
    a1 = fmaf(fs0.y, di2, a1);
    a2 = fmaf(fs1.x, di2, a2);
    a3 = fmaf(fs1.y, di2, a3);
    const float4 b = *(const float4*)(bias + col);
    a0 = fmaxf(a0 + b.x, 0.f);
    a1 = fmaxf(a1 + b.y, 0.f);
    a2 = fmaxf(a2 + b.z, 0.f);
    a3 = fmaxf(a3 + b.w, 0.f);
    uint2 outv;
    *(__nv_bfloat162*)&outv.x = __float22bfloat162_rn(make_float2(a0, a1));
    *(__nv_bfloat162*)&outv.y = __float22bfloat162_rn(make_float2(a2, a3));
    *(uint2*)(h + (size_t)node * HH + col) = outv;
}

// ---------------- final layer ------------------------------------------------
__global__ void head_final_kernel(const __nv_bfloat16* __restrict__ z3,
                                  const float* __restrict__ Wh4,
                                  const float* __restrict__ bh4,
                                  float* __restrict__ out) {
    int gtid = blockIdx.x * blockDim.x + threadIdx.x;
    int r = gtid >> 5;
    if (r >= BB) return;
    int lane = gtid & 31;
    const __nv_bfloat16* zr = z3 + (size_t)r * 64;
    float s = __bfloat162float(zr[lane]) * Wh4[lane]
            + __bfloat162float(zr[32 + lane]) * Wh4[32 + lane];
    #pragma unroll
    for (int o = 16; o; o >>= 1) s += __shfl_xor_sync(0xFFFFFFFFu, s, o);
    if (lane == 0) {
        float v = s + bh4[0];
        out[r] = 1.0f / (1.0f + expf(-v));
    }
}

// =============================================================================
extern "C" void kernel_launch(void* const* d_in, const int* in_sizes, int n_in,
                              void* d_out, int out_size) {
    const float* x          = (const float*)d_in[0];
    const int*   edge_index = (const int*)  d_in[1];
    const int*   origin_ids = (const int*)  d_in[2];
    const int*   dest_ids   = (const int*)  d_in[3];
    const int*   day_ids    = (const int*)  d_in[4];
    const int*   time_ids   = (const int*)  d_in[5];
    const int*   mode_ids   = (const int*)  d_in[6];
    const float* W1 = (const float*)d_in[7];
    const float* b1 = (const float*)d_in[8];
    const float* W2 = (const float*)d_in[9];
    const float* b2 = (const float*)d_in[10];
    const float* W3 = (const float*)d_in[11];
    const float* b3 = (const float*)d_in[12];
    const float* day_table  = (const float*)d_in[13];
    const float* time_table = (const float*)d_in[14];
    const float* mode_table = (const float*)d_in[15];
    const float* Wf  = (const float*)d_in[16];
    const float* bf  = (const float*)d_in[17];
    const float* Wh1 = (const float*)d_in[18];
    const float* bh1 = (const float*)d_in[19];
    const float* Wh2 = (const float*)d_in[20];
    const float* bh2 = (const float*)d_in[21];
    const float* Wh3 = (const float*)d_in[22];
    const float* bh3 = (const float*)d_in[23];
    const float* Wh4 = (const float*)d_in[24];
    const float* bh4 = (const float*)d_in[25];
    float* out = (float*)d_out;

    const int* srcE = edge_index;
    const int* dstE = edge_index + EE;

    float *dinv, *csr_coef;
    int *cnt, *rowp, *cursor, *bsum, *csr_src;
    __nv_bfloat16 *wt, *hw, *h, *temp, *z1, *z2, *z3;
    cudaGetSymbolAddress((void**)&dinv, g_dinv);
    cudaGetSymbolAddress((void**)&cnt,  g_cnt);
    cudaGetSymbolAddress((void**)&rowp, g_rowp);
    cudaGetSymbolAddress((void**)&cursor, g_cursor);
    cudaGetSymbolAddress((void**)&bsum, g_bsum);
    cudaGetSymbolAddress((void**)&csr_src,  g_csr_src);
    cudaGetSymbolAddress((void**)&csr_coef, g_csr_coef);
    cudaGetSymbolAddress((void**)&wt,   g_wt);
    cudaGetSymbolAddress((void**)&hw,   g_hw);
    cudaGetSymbolAddress((void**)&h,    g_h);
    cudaGetSymbolAddress((void**)&temp, g_temp);
    cudaGetSymbolAddress((void**)&z1,   g_z1);
    cudaGetSymbolAddress((void**)&z2,   g_z2);
    cudaGetSymbolAddress((void**)&z3,   g_z3);

    const int T = 256;

    // --- weight transpose/convert (once) ---
    WtParams WP;
    WP.seg[0] = { W1,  128, 128, OFF_W1 };
    WP.seg[1] = { W2,  128, 128, OFF_W2 };
    WP.seg[2] = { W3,  128, 128, OFF_W3 };
    WP.seg[3] = { Wf,  128, 128, OFF_WF };
    WP.seg[4] = { Wh1, 448, 256, OFF_WH1 };
    WP.seg[5] = { Wh2, 256, 128, OFF_WH2 };
    WP.seg[6] = { Wh3, 128, 64,  OFF_WH3 };
    wt_build_kernel<<<(WT_TOTAL + T - 1) / T, T>>>(WP, wt);

    // --- CSR build (once) ---
    cudaMemsetAsync(cnt, 0, NN * sizeof(int));
    cnt_count_kernel<<<((EE + 3) / 4 + T - 1) / T, T>>>(dstE, cnt);
    dinv_kernel<<<(NN + T - 1) / T, T>>>(cnt, dinv);
    scan_block_kernel<<<NBLK_SCAN, SCAN_B>>>(cnt, rowp, bsum);
    scan_bsum_kernel<<<1, 128>>>(bsum);
    scan_add_kernel<<<(NN + T - 1) / T, T>>>(rowp, bsum, cursor);
    scatter_kernel<<<(EE + T - 1) / T, T>>>(srcE, dstE, dinv, cursor, csr_src, csr_coef);

    dim3 blk(256);
    dim3 gNode(1, (NN + 127) / 128);
    dim3 gHead(1, (BB + 127) / 128);
    int aggBlocks = (NN + 7) / 8;

    GParams P = {};
    P.h = h; P.temp = temp;
    P.day_table = day_table; P.time_table = time_table; P.mode_table = mode_table;
    P.orig = origin_ids; P.dest = dest_ids;
    P.day_ids = day_ids; P.time_ids = time_ids; P.mode_ids = mode_ids;

    // --- GCN layers ---
    GParams Pa = P; Pa.A = x;
    tc_gemm_kernel<0><<<gNode, blk>>>(Pa, wt + OFF_W1, nullptr, hw, NN, FF, HH, 0);
    agg_fused_kernel<<<aggBlocks, T>>>(rowp, csr_src, csr_coef, dinv, hw, b1, h);
    Pa.A = h;
    tc_gemm_kernel<1><<<gNode, blk>>>(Pa, wt + OFF_W2, nullptr, hw, NN, HH, HH, 0);
    agg_fused_kernel<<<aggBlocks, T>>>(rowp, csr_src, csr_coef, dinv, hw, b2, h);
    tc_gemm_kernel<1><<<gNode, blk>>>(Pa, wt + OFF_W3, nullptr, hw, NN, HH, HH, 0);
    agg_fused_kernel<<<aggBlocks, T>>>(rowp, csr_src, csr_coef, dinv, hw, b3, h);

    // --- temporal fusion ---
    tc_gemm_kernel<3><<<gHead, blk>>>(P, wt + OFF_WF, bf, temp, BB, HH, HH, 1);

    // --- prediction head ---
    dim3 gZ1(2, (BB + 127) / 128);
    tc_gemm_kernel<2><<<gZ1, blk>>>(P, wt + OFF_WH1, bh1, z1, BB, PIN, 256, 1);
    GParams Pz = P; Pz.A = z1;
    tc_gemm_kernel<1><<<gHead, blk>>>(Pz, wt + OFF_WH2, bh2, z2, BB, 256, 128, 1);
    Pz.A = z2;
    tc_gemm_kernel<1><<<gHead, blk>>>(Pz, wt + OFF_WH3, bh3, z3, BB, 128, 64, 1);

    head_final_kernel<<<(int)(((size_t)BB * 32 + T - 1) / T), T>>>(z3, Wh4, bh4, out);
}

// round 7
// speedup vs baseline: 8.6326x; 1.1015x over previous
#include <cuda_runtime.h>
#include <cuda_bf16.h>
#include <math.h>
#include <cstdint>

// Problem constants
#define NN 100000      // nodes
#define FF 128         // node features
#define HH 128         // hidden
#define EE 1600000     // edges
#define BB 65536       // queries
#define TD 64          // H/2
#define PIN 448        // 2H + H + TD

#define SCAN_B 1024
#define NBLK_SCAN ((NN + SCAN_B - 1) / SCAN_B)   // 98

// bf16 transposed-weight pool offsets (Wt[n][k], row stride = K)
#define OFF_W1  0
#define OFF_W2  16384
#define OFF_W3  32768
#define OFF_WF  49152
#define OFF_WH1 65536          // 256 rows x 448
#define OFF_WH2 180224         // 128 rows x 256
#define OFF_WH3 212992         // 64 rows x 128
#define WT_TOTAL 221184

// ---------------- scratch (static device memory; no allocation) --------------
__device__ float g_dinv[NN];
__device__ int   g_cnt  [NN];
__device__ int   g_rowp [NN + 1];
__device__ int   g_cursor[NN];
__device__ int   g_bsum [NBLK_SCAN + 1];
__device__ int   g_csr_src [EE];
__device__ __nv_bfloat16 g_wt  [WT_TOTAL];
__device__ __nv_bfloat16 g_hw  [(size_t)NN * HH];   // u = (h@W) * dinv[row]
__device__ __nv_bfloat16 g_h   [(size_t)NN * HH];
__device__ __nv_bfloat16 g_temp[(size_t)BB * HH];
__device__ __nv_bfloat16 g_z1  [(size_t)BB * 256];
__device__ __nv_bfloat16 g_z2  [(size_t)BB * 128];
__device__ __nv_bfloat16 g_z3  [(size_t)BB * 64];

// ======================= HMMA helpers ========================================
__device__ __forceinline__ uint32_t smem_to_u32(const void* p) {
    uint32_t a;
    asm("{ .reg .u64 t; cvta.to.shared.u64 t, %1; cvt.u32.u64 %0, t; }"
        : "=r"(a) : "l"(p));
    return a;
}
__device__ __forceinline__ void ldm_x4(uint32_t& r0, uint32_t& r1,
                                       uint32_t& r2, uint32_t& r3, uint32_t addr) {
    asm volatile("ldmatrix.sync.aligned.m8n8.x4.shared.b16 {%0,%1,%2,%3}, [%4];"
        : "=r"(r0), "=r"(r1), "=r"(r2), "=r"(r3) : "r"(addr));
}
__device__ __forceinline__ void mma_bf16(float* c, const uint32_t* a,
                                         uint32_t b0, uint32_t b1) {
    asm volatile(
        "mma.sync.aligned.m16n8k16.row.col.f32.bf16.bf16.f32 "
        "{%0,%1,%2,%3}, {%4,%5,%6,%7}, {%8,%9}, {%0,%1,%2,%3};"
        : "+f"(c[0]), "+f"(c[1]), "+f"(c[2]), "+f"(c[3])
        : "r"(a[0]), "r"(a[1]), "r"(a[2]), "r"(a[3]), "r"(b0), "r"(b1));
}

// ============ weight transpose + bf16 convert (once per launch) ==============
struct WtSeg { const float* src; int K; int N; int off; };
struct WtParams { WtSeg seg[7]; };

__global__ void wt_build_kernel(WtParams P, __nv_bfloat16* wt) {
    int idx = blockIdx.x * blockDim.x + threadIdx.x;
    if (idx >= WT_TOTAL) return;
    #pragma unroll
    for (int s = 0; s < 7; s++) {
        int sz = P.seg[s].K * P.seg[s].N;
        if (idx < P.seg[s].off + sz) {
            int li = idx - P.seg[s].off;
            int K = P.seg[s].K;
            int n = li / K, k = li - n * K;
            wt[idx] = __float2bfloat16(P.seg[s].src[(size_t)k * P.seg[s].N + n]);
            return;
        }
    }
}

// ======================= tensor-core GEMM ====================================
// C[M, Ntot] = A[M, K] @ W[K, Ntot]; Wt is bf16 transposed: Wt[n][k], stride K.
// ASRC: 0 = fp32 dense, 1 = bf16 dense, 2 = head1 gather (K=448), 3 = tin gather
// mode 0: C = v   mode 1: C = relu(v + bias)   mode 2: C = v * dinv[row]
#define LDBYTES 144

struct GParams {
    const void* A;
    const __nv_bfloat16* h;
    const __nv_bfloat16* temp;
    const float* day_table; const float* time_table; const float* mode_table;
    const int* orig; const int* dest; const int* day_ids; const int* time_ids;
    const int* mode_ids;
};

template<int ASRC>
__global__ void __launch_bounds__(256, 2)
tc_gemm_kernel(GParams P, const __nv_bfloat16* __restrict__ Wt,
               const float* __restrict__ bias, const float* __restrict__ dinv,
               __nv_bfloat16* __restrict__ C,
               int M, int K, int Ntot, int mode) {
    __shared__ __align__(16) char smem[2 * 128 * LDBYTES];
    char* sA = smem;
    char* sB = smem + 128 * LDBYTES;
    uint32_t sAu = smem_to_u32(sA);
    uint32_t sBu = smem_to_u32(sB);

    int tid = threadIdx.x;
    int wid = tid >> 5;
    int lane = tid & 31;
    int wm = wid >> 1;
    int wn = wid & 1;

    int rowBase = blockIdx.y * 128;
    int colBase = blockIdx.x * 128;

    float acc[2][8][4];
    #pragma unroll
    for (int mt = 0; mt < 2; mt++)
        #pragma unroll
        for (int nf = 0; nf < 8; nf++)
            #pragma unroll
            for (int j = 0; j < 4; j++) acc[mt][nf][j] = 0.0f;

    int lq = lane & 15;
    int lh = lane >> 4;

    for (int k0 = 0; k0 < K; k0 += 64) {
        __syncthreads();
        // ---- A tile staging: 128 rows x 64 bf16 ----
        if (ASRC == 0) {
            const float* A = (const float*)P.A;
            #pragma unroll 4
            for (int i = tid; i < 128 * 32; i += 256) {
                int r = i >> 5, kp = i & 31;
                int gr = rowBase + r;
                float2 v = make_float2(0.f, 0.f);
                if (gr < M) v = *(const float2*)(A + (size_t)gr * K + k0 + 2 * kp);
                *(__nv_bfloat162*)(sA + r * LDBYTES + kp * 4) = __float22bfloat162_rn(v);
            }
        } else if (ASRC == 1) {
            const __nv_bfloat16* A = (const __nv_bfloat16*)P.A;
            #pragma unroll 4
            for (int i = tid; i < 128 * 8; i += 256) {
                int r = i >> 3, seg = i & 7;
                int gr = rowBase + r;
                uint4 v = make_uint4(0, 0, 0, 0);
                if (gr < M) v = *(const uint4*)(A + (size_t)gr * K + k0 + seg * 8);
                *(uint4*)(sA + r * LDBYTES + seg * 16) = v;
            }
        } else if (ASRC == 2) {
            if (k0 < 384) {
                #pragma unroll 4
                for (int i = tid; i < 128 * 8; i += 256) {
                    int r = i >> 3, seg = i & 7;
                    int gr = rowBase + r;
                    const __nv_bfloat16* srcp;
                    if (k0 < 128)       srcp = P.h + (size_t)P.orig[gr] * HH + k0;
                    else if (k0 < 256)  srcp = P.h + (size_t)P.dest[gr] * HH + (k0 - 128);
                    else                srcp = P.temp + (size_t)gr * HH + (k0 - 256);
                    *(uint4*)(sA + r * LDBYTES + seg * 16) = *(const uint4*)(srcp + seg * 8);
                }
            } else {
                #pragma unroll 4
                for (int i = tid; i < 128 * 32; i += 256) {
                    int r = i >> 5, kp = i & 31;
                    int gr = rowBase + r;
                    const float* srcp = P.mode_table + (size_t)P.mode_ids[gr] * TD;
                    float2 v = *(const float2*)(srcp + 2 * kp);
                    *(__nv_bfloat162*)(sA + r * LDBYTES + kp * 4) = __float22bfloat162_rn(v);
                }
            }
        } else {
            #pragma unroll 4
            for (int i = tid; i < 128 * 32; i += 256) {
                int r = i >> 5, kp = i & 31;
                int gr = rowBase + r;
                const float* srcp = (k0 == 0)
                    ? P.day_table  + (size_t)P.day_ids[gr]  * TD
                    : P.time_table + (size_t)P.time_ids[gr] * TD;
                float2 v = *(const float2*)(srcp + 2 * kp);
                *(__nv_bfloat162*)(sA + r * LDBYTES + kp * 4) = __float22bfloat162_rn(v);
            }
        }
        // ---- B tile: 128 n-rows x 64 bf16 from transposed bf16 weights ----
        #pragma unroll 4
        for (int i = tid; i < 128 * 8; i += 256) {
            int n = i >> 3, seg = i & 7;
            int gc = colBase + n;
            uint4 v = make_uint4(0, 0, 0, 0);
            if (gc < Ntot) v = *(const uint4*)(Wt + (size_t)gc * K + k0 + seg * 8);
            *(uint4*)(sB + n * LDBYTES + seg * 16) = v;
        }
        __syncthreads();

        #pragma unroll
        for (int ks = 0; ks < 4; ks++) {
            uint32_t af[2][4];
            #pragma unroll
            for (int mt = 0; mt < 2; mt++) {
                uint32_t addr = sAu + (uint32_t)(wm * 32 + mt * 16 + lq) * LDBYTES
                              + ks * 32 + lh * 16;
                ldm_x4(af[mt][0], af[mt][1], af[mt][2], af[mt][3], addr);
            }
            uint32_t bfr[8][2];
            #pragma unroll
            for (int g = 0; g < 4; g++) {
                uint32_t r0, r1, r2, r3;
                uint32_t addr = sBu + (uint32_t)(wn * 64 + g * 16 + lq) * LDBYTES
                              + ks * 32 + lh * 16;
                ldm_x4(r0, r1, r2, r3, addr);
                bfr[2 * g][0] = r0;     bfr[2 * g][1] = r2;
                bfr[2 * g + 1][0] = r1; bfr[2 * g + 1][1] = r3;
            }
            #pragma unroll
            for (int mt = 0; mt < 2; mt++)
                #pragma unroll
                for (int nf = 0; nf < 8; nf++)
                    mma_bf16(acc[mt][nf], af[mt], bfr[nf][0], bfr[nf][1]);
        }
    }

    int rowOff = lane >> 2;
    int colOff = (lane & 3) * 2;
    #pragma unroll
    for (int mt = 0; mt < 2; mt++) {
        #pragma unroll
        for (int half = 0; half < 2; half++) {
            int r = rowBase + wm * 32 + mt * 16 + rowOff + half * 8;
            if (r >= M) continue;
            float dsc = (mode == 2) ? dinv[r] : 1.0f;
            #pragma unroll
            for (int nf = 0; nf < 8; nf++) {
                int c = colBase + wn * 64 + nf * 8 + colOff;
                if (c >= Ntot) continue;
                float v0 = acc[mt][nf][half * 2 + 0];
                float v1 = acc[mt][nf][half * 2 + 1];
                if (mode == 1) {
                    v0 = fmaxf(v0 + bias[c], 0.f);
                    v1 = fmaxf(v1 + bias[c + 1], 0.f);
                } else if (mode == 2) {
                    v0 *= dsc;
                    v1 *= dsc;
                }
                *(__nv_bfloat162*)(C + (size_t)r * Ntot + c) =
                    __float22bfloat162_rn(make_float2(v0, v1));
            }
        }
    }
}

// ======================= CSR build ===========================================
__global__ void cnt_count_kernel(const int* __restrict__ dst, int* cnt) {
    int i = blockIdx.x * blockDim.x + threadIdx.x;
    int e = i * 4;
    if (e + 3 < EE) {
        int4 d = *(const int4*)(dst + e);
        atomicAdd(&cnt[d.x], 1);
        atomicAdd(&cnt[d.y], 1);
        atomicAdd(&cnt[d.z], 1);
        atomicAdd(&cnt[d.w], 1);
    } else {
        for (int k = e; k < EE; k++) atomicAdd(&cnt[dst[k]], 1);
    }
}
__global__ void dinv_kernel(const int* __restrict__ cnt, float* dinv) {
    int i = blockIdx.x * blockDim.x + threadIdx.x;
    if (i < NN) dinv[i] = rsqrtf((float)cnt[i] + 1.0f);
}
__global__ void scan_block_kernel(const int* __restrict__ cnt, int* excl, int* bsum) {
    __shared__ int s[SCAN_B];
    int tid = threadIdx.x;
    int i = blockIdx.x * SCAN_B + tid;
    int v = (i < NN) ? cnt[i] : 0;
    s[tid] = v;
    __syncthreads();
    for (int off = 1; off < SCAN_B; off <<= 1) {
        int t = (tid >= off) ? s[tid - off] : 0;
        __syncthreads();
        s[tid] += t;
        __syncthreads();
    }
    if (i < NN) excl[i] = s[tid] - v;
    if (tid == SCAN_B - 1) bsum[blockIdx.x] = s[tid];
}
__global__ void scan_bsum_kernel(int* bsum) {
    __shared__ int s[NBLK_SCAN];
    int tid = threadIdx.x;
    if (tid < NBLK_SCAN) s[tid] = bsum[tid];
    __syncthreads();
    if (tid == 0) {
        int run = 0;
        for (int b = 0; b < NBLK_SCAN; b++) { int t = s[b]; s[b] = run; run += t; }
    }
    __syncthreads();
    if (tid < NBLK_SCAN) bsum[tid] = s[tid];
}
__global__ void scan_add_kernel(int* rowp, const int* __restrict__ bsum, int* cursor) {
    int i = blockIdx.x * blockDim.x + threadIdx.x;
    if (i < NN) {
        int v = rowp[i] + bsum[i / SCAN_B];
        rowp[i] = v;
        cursor[i] = v;
    }
    if (i == 0) rowp[NN] = EE;
}
__global__ void scatter_kernel(const int* __restrict__ src, const int* __restrict__ dst,
                               int* cursor, int* csr_src) {
    int i = blockIdx.x * blockDim.x + threadIdx.x;
    int e = i * 4;
    if (e + 3 < EE) {
        int4 s4 = *(const int4*)(src + e);
        int4 d4 = *(const int4*)(dst + e);
        csr_src[atomicAdd(&cursor[d4.x], 1)] = s4.x;
        csr_src[atomicAdd(&cursor[d4.y], 1)] = s4.y;
        csr_src[atomicAdd(&cursor[d4.z], 1)] = s4.z;
        csr_src[atomicAdd(&cursor[d4.w], 1)] = s4.w;
    } else {
        for (int k = e; k < EE; k++)
            csr_src[atomicAdd(&cursor[dst[k]], 1)] = src[k];
    }
}

// ====== fused aggregation: h = relu(dinv[d]*(sum_src u[src] + u[d]) + b) =====
// u = (h@W)*dinv  produced by GEMM mode 2. One warp per node; lane owns 4 cols.
__global__ void __launch_bounds__(256)
agg_fused_kernel(const int* __restrict__ rowp,
                 const int* __restrict__ csr_src,
                 const float* __restrict__ dinv,
                 const __nv_bfloat16* __restrict__ u,
                 const float* __restrict__ bias,
                 __nv_bfloat16* __restrict__ h) {
    int node = (blockIdx.x * blockDim.x + threadIdx.x) >> 5;
    if (node >= NN) return;
    int lane = threadIdx.x & 31;
    int col = lane * 4;

    int beg = rowp[node], end = rowp[node + 1];
    float a0 = 0.f, a1 = 0.f, a2 = 0.f, a3 = 0.f;
    for (int i = beg; i < end; i += 32) {
        int n = end - i; if (n > 32) n = 32;
        int sidx = 0;
        if (lane < n) sidx = csr_src[i + lane];
        #pragma unroll 4
        for (int j = 0; j < n; j++) {
            int s = __shfl_sync(0xFFFFFFFFu, sidx, j);
            uint2 raw = *(const uint2*)(u + (size_t)s * HH + col);
            float2 f0 = __bfloat1622float2(*(__nv_bfloat162*)&raw.x);
            float2 f1 = __bfloat1622float2(*(__nv_bfloat162*)&raw.y);
            a0 += f0.x; a1 += f0.y; a2 += f1.x; a3 += f1.y;
        }
    }
    uint2 raws = *(const uint2*)(u + (size_t)node * HH + col);
    float2 fs0 = __bfloat1622float2(*(__nv_bfloat162*)&raws.x);
    float2 fs1 = __bfloat1622float2(*(__nv_bfloat162*)&raws.y);
    a0 += fs0.x; a1 += fs0.y; a2 += fs1.x; a3 += fs1.y;

    float di = dinv[node];
    const float4 b = *(const float4*)(bias + col);
    a0 = fmaxf(fmaf(a0, di, b.x), 0.f);
    a1 = fmaxf(fmaf(a1, di, b.y), 0.f);
    a2 = fmaxf(fmaf(a2, di, b.z), 0.f);
    a3 = fmaxf(fmaf(a3, di, b.w), 0.f);
    uint2 outv;
    *(__nv_bfloat162*)&outv.x = __float22bfloat162_rn(make_float2(a0, a1));
    *(__nv_bfloat162*)&outv.y = __float22bfloat162_rn(make_float2(a2, a3));
    *(uint2*)(h + (size_t)node * HH + col) = outv;
}

// ---------------- final layer ------------------------------------------------
__global__ void head_final_kernel(const __nv_bfloat16* __restrict__ z3,
                                  const float* __restrict__ Wh4,
                                  const float* __restrict__ bh4,
                                  float* __restrict__ out) {
    int gtid = blockIdx.x * blockDim.x + threadIdx.x;
    int r = gtid >> 5;
    if (r >= BB) return;
    int lane = gtid & 31;
    const __nv_bfloat16* zr = z3 + (size_t)r * 64;
    float s = __bfloat162float(zr[lane]) * Wh4[lane]
            + __bfloat162float(zr[32 + lane]) * Wh4[32 + lane];
    #pragma unroll
    for (int o = 16; o; o >>= 1) s += __shfl_xor_sync(0xFFFFFFFFu, s, o);
    if (lane == 0) {
        float v = s + bh4[0];
        out[r] = 1.0f / (1.0f + expf(-v));
    }
}

// =============================================================================
extern "C" void kernel_launch(void* const* d_in, const int* in_sizes, int n_in,
                              void* d_out, int out_size) {
    const float* x          = (const float*)d_in[0];
    const int*   edge_index = (const int*)  d_in[1];
    const int*   origin_ids = (const int*)  d_in[2];
    const int*   dest_ids   = (const int*)  d_in[3];
    const int*   day_ids    = (const int*)  d_in[4];
    const int*   time_ids   = (const int*)  d_in[5];
    const int*   mode_ids   = (const int*)  d_in[6];
    const float* W1 = (const float*)d_in[7];
    const float* b1 = (const float*)d_in[8];
    const float* W2 = (const float*)d_in[9];
    const float* b2 = (const float*)d_in[10];
    const float* W3 = (const float*)d_in[11];
    const float* b3 = (const float*)d_in[12];
    const float* day_table  = (const float*)d_in[13];
    const float* time_table = (const float*)d_in[14];
    const float* mode_table = (const float*)d_in[15];
    const float* Wf  = (const float*)d_in[16];
    const float* bf  = (const float*)d_in[17];
    const float* Wh1 = (const float*)d_in[18];
    const float* bh1 = (const float*)d_in[19];
    const float* Wh2 = (const float*)d_in[20];
    const float* bh2 = (const float*)d_in[21];
    const float* Wh3 = (const float*)d_in[22];
    const float* bh3 = (const float*)d_in[23];
    const float* Wh4 = (const float*)d_in[24];
    const float* bh4 = (const float*)d_in[25];
    float* out = (float*)d_out;

    const int* srcE = edge_index;
    const int* dstE = edge_index + EE;

    float* dinv;
    int *cnt, *rowp, *cursor, *bsum, *csr_src;
    __nv_bfloat16 *wt, *hw, *h, *temp, *z1, *z2, *z3;
    cudaGetSymbolAddress((void**)&dinv, g_dinv);
    cudaGetSymbolAddress((void**)&cnt,  g_cnt);
    cudaGetSymbolAddress((void**)&rowp, g_rowp);
    cudaGetSymbolAddress((void**)&cursor, g_cursor);
    cudaGetSymbolAddress((void**)&bsum, g_bsum);
    cudaGetSymbolAddress((void**)&csr_src,  g_csr_src);
    cudaGetSymbolAddress((void**)&wt,   g_wt);
    cudaGetSymbolAddress((void**)&hw,   g_hw);
    cudaGetSymbolAddress((void**)&h,    g_h);
    cudaGetSymbolAddress((void**)&temp, g_temp);
    cudaGetSymbolAddress((void**)&z1,   g_z1);
    cudaGetSymbolAddress((void**)&z2,   g_z2);
    cudaGetSymbolAddress((void**)&z3,   g_z3);

    // --- side stream + events (created once; host-side handles only) ---
    static cudaStream_t sSide = nullptr;
    static cudaEvent_t evRoot = nullptr, evDinv = nullptr, evCSR = nullptr;
    if (!sSide) {
        cudaStreamCreateWithFlags(&sSide, cudaStreamNonBlocking);
        cudaEventCreateWithFlags(&evRoot, cudaEventDisableTiming);
        cudaEventCreateWithFlags(&evDinv, cudaEventDisableTiming);
        cudaEventCreateWithFlags(&evCSR,  cudaEventDisableTiming);
    }

    const int T = 256;

    // ---- fork: CSR build on side stream ----
    cudaEventRecord(evRoot, 0);
    cudaStreamWaitEvent(sSide, evRoot, 0);
    cudaMemsetAsync(cnt, 0, NN * sizeof(int), sSide);
    cnt_count_kernel<<<((EE + 3) / 4 + T - 1) / T, T, 0, sSide>>>(dstE, cnt);
    dinv_kernel<<<(NN + T - 1) / T, T, 0, sSide>>>(cnt, dinv);
    cudaEventRecord(evDinv, sSide);
    scan_block_kernel<<<NBLK_SCAN, SCAN_B, 0, sSide>>>(cnt, rowp, bsum);
    scan_bsum_kernel<<<1, 128, 0, sSide>>>(bsum);
    scan_add_kernel<<<(NN + T - 1) / T, T, 0, sSide>>>(rowp, bsum, cursor);
    scatter_kernel<<<((EE + 3) / 4 + T - 1) / T, T, 0, sSide>>>(srcE, dstE, cursor, csr_src);
    cudaEventRecord(evCSR, sSide);

    // ---- main stream: weights + CSR-independent GEMMs ----
    WtParams WP;
    WP.seg[0] = { W1,  128, 128, OFF_W1 };
    WP.seg[1] = { W2,  128, 128, OFF_W2 };
    WP.seg[2] = { W3,  128, 128, OFF_W3 };
    WP.seg[3] = { Wf,  128, 128, OFF_WF };
    WP.seg[4] = { Wh1, 448, 256, OFF_WH1 };
    WP.seg[5] = { Wh2, 256, 128, OFF_WH2 };
    WP.seg[6] = { Wh3, 128, 64,  OFF_WH3 };
    wt_build_kernel<<<(WT_TOTAL + T - 1) / T, T>>>(WP, wt);

    dim3 blk(256);
    dim3 gNode(1, (NN + 127) / 128);
    dim3 gHead(1, (BB + 127) / 128);
    int aggBlocks = (NN + 7) / 8;

    GParams P = {};
    P.h = h; P.temp = temp;
    P.day_table = day_table; P.time_table = time_table; P.mode_table = mode_table;
    P.orig = origin_ids; P.dest = dest_ids;
    P.day_ids = day_ids; P.time_ids = time_ids; P.mode_ids = mode_ids;

    // temporal GEMM: independent of graph
    tc_gemm_kernel<3><<<gHead, blk>>>(P, wt + OFF_WF, bf, nullptr, temp, BB, HH, HH, 1);

    // GEMM1 needs dinv only
    cudaStreamWaitEvent(0, evDinv, 0);
    GParams Pa = P; Pa.A = x;
    tc_gemm_kernel<0><<<gNode, blk>>>(Pa, wt + OFF_W1, nullptr, dinv, hw, NN, FF, HH, 2);

    // join: aggregation needs the CSR
    cudaStreamWaitEvent(0, evCSR, 0);
    agg_fused_kernel<<<aggBlocks, T>>>(rowp, csr_src, dinv, hw, b1, h);
    Pa.A = h;
    tc_gemm_kernel<1><<<gNode, blk>>>(Pa, wt + OFF_W2, nullptr, dinv, hw, NN, HH, HH, 2);
    agg_fused_kernel<<<aggBlocks, T>>>(rowp, csr_src, dinv, hw, b2, h);
    tc_gemm_kernel<1><<<gNode, blk>>>(Pa, wt + OFF_W3, nullptr, dinv, hw, NN, HH, HH, 2);
    agg_fused_kernel<<<aggBlocks, T>>>(rowp, csr_src, dinv, hw, b3, h);

    // --- prediction head ---
    dim3 gZ1(2, (BB + 127) / 128);
    tc_gemm_kernel<2><<<gZ1, blk>>>(P, wt + OFF_WH1, bh1, nullptr, z1, BB, PIN, 256, 1);
    GParams Pz = P; Pz.A = z1;
    tc_gemm_kernel<1><<<gHead, blk>>>(Pz, wt + OFF_WH2, bh2, nullptr, z2, BB, 256, 128, 1);
    Pz.A = z2;
    tc_gemm_kernel<1><<<gHead, blk>>>(Pz, wt + OFF_WH3, bh3, nullptr, z3, BB, 128, 64, 1);

    head_final_kernel<<<(int)(((size_t)BB * 32 + T - 1) / T), T>>>(z3, Wh4, bh4, out);
}